// round 1
// baseline (speedup 1.0000x reference)
#include <cuda_runtime.h>
#include <math.h>

#define NB    4
#define NTOK  4096
#define CDIM  1024
#define NH    16
#define HD    64
#define NBH   (NB * NH)        // 64
#define MTOT  (NB * NTOK)      // 16384

// Scratch (device globals -- no runtime allocation allowed)
__device__ float g_q[NBH * NTOK * HD];       // 64 MB  [bh][n][d]  (elu+1 applied)
__device__ float g_k[NBH * NTOK * HD];       // 64 MB
__device__ float g_v[NBH * NTOK * HD];       // 64 MB
__device__ float g_kv[NBH * HD * HD];        // 1 MB   [bh][d][e]
__device__ float g_ksum[NBH * HD];           //        [bh][d]
__device__ float g_attn[MTOT * CDIM];        // 64 MB  [b*n][c]

__device__ __forceinline__ float elu1(float x) {
    return x > 0.f ? x + 1.f : expf(x);   // elu(x)+1
}

// ---------------------------------------------------------------------------
// Stage A: qkv = x @ w_qkv^T, scatter to g_q/g_k/g_v with feature map.
// A[M,K] row-major, W[N,K] row-major (NT GEMM). 128x128x8 tile, 8x8/thread.
// ---------------------------------------------------------------------------
__global__ __launch_bounds__(256, 2) void gemm_qkv(const float* __restrict__ A,
                                                   const float* __restrict__ W) {
    __shared__ __align__(16) float As[8][128];
    __shared__ __align__(16) float Bs[8][128];
    const int tid = threadIdx.x;
    const int m0 = blockIdx.y * 128;
    const int n0 = blockIdx.x * 128;
    const int lr = tid >> 1;
    const int lc = (tid & 1) * 4;
    const float* Ag = A + (m0 + lr) * CDIM + lc;
    const float* Bg = W + (n0 + lr) * CDIM + lc;
    const int tx = tid & 15;
    const int ty = tid >> 4;

    float acc[8][8];
#pragma unroll
    for (int i = 0; i < 8; i++)
#pragma unroll
        for (int j = 0; j < 8; j++) acc[i][j] = 0.f;

    for (int k0 = 0; k0 < CDIM; k0 += 8) {
        float4 a4 = *(const float4*)(Ag + k0);
        float4 b4 = *(const float4*)(Bg + k0);
        As[lc + 0][lr] = a4.x; As[lc + 1][lr] = a4.y;
        As[lc + 2][lr] = a4.z; As[lc + 3][lr] = a4.w;
        Bs[lc + 0][lr] = b4.x; Bs[lc + 1][lr] = b4.y;
        Bs[lc + 2][lr] = b4.z; Bs[lc + 3][lr] = b4.w;
        __syncthreads();
#pragma unroll
        for (int kk = 0; kk < 8; kk++) {
            float af[8], bf[8];
            *(float4*)(af)     = *(const float4*)&As[kk][ty * 8];
            *(float4*)(af + 4) = *(const float4*)&As[kk][ty * 8 + 4];
            *(float4*)(bf)     = *(const float4*)&Bs[kk][tx * 8];
            *(float4*)(bf + 4) = *(const float4*)&Bs[kk][tx * 8 + 4];
#pragma unroll
            for (int i = 0; i < 8; i++)
#pragma unroll
                for (int j = 0; j < 8; j++) acc[i][j] += af[i] * bf[j];
        }
        __syncthreads();
    }

    // Epilogue: n in [0,3072). part = n/1024 (q/k/v), h = (n%1024)/64, d = n%64.
    // BN=128 divides 1024 so the whole block is a single part.
    const int part = n0 >> 10;
    float* dst = (part == 0) ? g_q : (part == 1) ? g_k : g_v;
    const int nb = (n0 & 1023) + tx * 8;   // within-part column base (8 consecutive)
    const int h  = nb >> 6;
    const int d0 = nb & 63;
#pragma unroll
    for (int i = 0; i < 8; i++) {
        int m = m0 + ty * 8 + i;
        int b = m >> 12;
        int t = m & 4095;
        float* p = dst + ((b * NH + h) * NTOK + t) * HD + d0;
        float4 o0, o1;
        if (part < 2) {
            o0 = make_float4(elu1(acc[i][0]), elu1(acc[i][1]), elu1(acc[i][2]), elu1(acc[i][3]));
            o1 = make_float4(elu1(acc[i][4]), elu1(acc[i][5]), elu1(acc[i][6]), elu1(acc[i][7]));
        } else {
            o0 = make_float4(acc[i][0], acc[i][1], acc[i][2], acc[i][3]);
            o1 = make_float4(acc[i][4], acc[i][5], acc[i][6], acc[i][7]);
        }
        *(float4*)p       = o0;
        *(float4*)(p + 4) = o1;
    }
}

// ---------------------------------------------------------------------------
// Stage B: per (b,h): kv[d][e] = sum_n k[n][d]*v[n][e]; ksum[d] = sum_n k[n][d]
// One block per bh; 16x16 threads, 4x4 micro-tile; tiles of 32 tokens.
// ---------------------------------------------------------------------------
__global__ __launch_bounds__(256) void kv_kernel() {
    __shared__ __align__(16) float ks[32][64];
    __shared__ __align__(16) float vs[32][64];
    const int tid = threadIdx.x;
    const int bh = blockIdx.x;
    const float* kp = g_k + bh * NTOK * HD;
    const float* vp = g_v + bh * NTOK * HD;
    const int lrow = tid >> 3;
    const int lcol = (tid & 7) * 8;
    const int tx = tid & 15, ty = tid >> 4;
    const int e0 = tx * 4, d0 = ty * 4;

    float acc[4][4];
#pragma unroll
    for (int i = 0; i < 4; i++)
#pragma unroll
        for (int j = 0; j < 4; j++) acc[i][j] = 0.f;
    float ksacc = 0.f;

    for (int n0 = 0; n0 < NTOK; n0 += 32) {
        __syncthreads();
        const float* kr = kp + (n0 + lrow) * HD + lcol;
        const float* vr = vp + (n0 + lrow) * HD + lcol;
        *(float4*)&ks[lrow][lcol]     = *(const float4*)kr;
        *(float4*)&ks[lrow][lcol + 4] = *(const float4*)(kr + 4);
        *(float4*)&vs[lrow][lcol]     = *(const float4*)vr;
        *(float4*)&vs[lrow][lcol + 4] = *(const float4*)(vr + 4);
        __syncthreads();
#pragma unroll 4
        for (int nn = 0; nn < 32; nn++) {
            float kf[4], vf[4];
            *(float4*)kf = *(const float4*)&ks[nn][d0];
            *(float4*)vf = *(const float4*)&vs[nn][e0];
#pragma unroll
            for (int i = 0; i < 4; i++)
#pragma unroll
                for (int j = 0; j < 4; j++) acc[i][j] += kf[i] * vf[j];
        }
        if (tid < 64) {
#pragma unroll 4
            for (int nn = 0; nn < 32; nn++) ksacc += ks[nn][tid];
        }
    }

    float* kvout = g_kv + bh * HD * HD;
#pragma unroll
    for (int i = 0; i < 4; i++) {
        float4 o = make_float4(acc[i][0], acc[i][1], acc[i][2], acc[i][3]);
        *(float4*)(kvout + (d0 + i) * HD + e0) = o;
    }
    if (tid < 64) g_ksum[bh * HD + tid] = ksacc;
}

// ---------------------------------------------------------------------------
// Stage C: per (b,h, tile of 128 rows): num = q @ kv; qk = q . ksum;
// attn[b,t,h*64+e] = num[e] / (qk + 1e-8).  One thread per row.
// Dynamic smem: qt (q transposed, stride 129), kvs, kss.
// ---------------------------------------------------------------------------
#define QT_STRIDE 129
#define SMEM_NUM_BYTES ((64 * QT_STRIDE + 64 * 64 + 64) * 4)

__global__ __launch_bounds__(128) void attn_num_kernel() {
    extern __shared__ float sm[];
    float* qt  = sm;                       // [64][129] transposed q tile
    float* kvs = sm + 64 * QT_STRIDE;      // [64][64]
    float* kss = kvs + 64 * 64;            // [64]
    const int tid = threadIdx.x;
    const int bh = blockIdx.y;
    const int b = bh >> 4, h = bh & 15;
    const int row0 = blockIdx.x * 128;
    const float* qp  = g_q + (bh * NTOK + row0) * HD;
    const float* kvp = g_kv + bh * HD * HD;

#pragma unroll
    for (int c = 0; c < 8; c++) {
        int g = (c * 128 + tid) * 4;
        *(float4*)&kvs[g] = *(const float4*)(kvp + g);
    }
    if (tid < 64) kss[tid] = g_ksum[bh * HD + tid];
#pragma unroll
    for (int c = 0; c < 16; c++) {
        int f = c * 128 + tid;
        float4 qv = *(const float4*)(qp + f * 4);
        int row = f >> 4;
        int col = (f & 15) * 4;
        qt[(col + 0) * QT_STRIDE + row] = qv.x;
        qt[(col + 1) * QT_STRIDE + row] = qv.y;
        qt[(col + 2) * QT_STRIDE + row] = qv.z;
        qt[(col + 3) * QT_STRIDE + row] = qv.w;
    }
    __syncthreads();

    float acc[64];
#pragma unroll
    for (int e = 0; e < 64; e++) acc[e] = 0.f;
    float qk = 0.f;
#pragma unroll 4
    for (int d = 0; d < 64; d++) {
        float qd = qt[d * QT_STRIDE + tid];
        qk += qd * kss[d];
        const float4* kr = (const float4*)&kvs[d * 64];
#pragma unroll
        for (int e4 = 0; e4 < 16; e4++) {
            float4 kv4 = kr[e4];
            acc[e4 * 4 + 0] += qd * kv4.x;
            acc[e4 * 4 + 1] += qd * kv4.y;
            acc[e4 * 4 + 2] += qd * kv4.z;
            acc[e4 * 4 + 3] += qd * kv4.w;
        }
    }

    float inv = 1.f / (qk + 1e-8f);
    float* op = g_attn + (b * NTOK + row0 + tid) * CDIM + h * HD;
#pragma unroll
    for (int e4 = 0; e4 < 16; e4++) {
        float4 o;
        o.x = acc[e4 * 4 + 0] * inv;
        o.y = acc[e4 * 4 + 1] * inv;
        o.z = acc[e4 * 4 + 2] * inv;
        o.w = acc[e4 * 4 + 3] * inv;
        *(float4*)(op + e4 * 4) = o;
    }
}

// ---------------------------------------------------------------------------
// Stage D: out = attn @ w_proj^T + b_proj. Same SGEMM, bias epilogue.
// ---------------------------------------------------------------------------
__global__ __launch_bounds__(256, 2) void gemm_proj(const float* __restrict__ W,
                                                    const float* __restrict__ bias,
                                                    float* __restrict__ out) {
    __shared__ __align__(16) float As[8][128];
    __shared__ __align__(16) float Bs[8][128];
    const int tid = threadIdx.x;
    const int m0 = blockIdx.y * 128;
    const int n0 = blockIdx.x * 128;
    const int lr = tid >> 1;
    const int lc = (tid & 1) * 4;
    const float* Ag = g_attn + (m0 + lr) * CDIM + lc;
    const float* Bg = W + (n0 + lr) * CDIM + lc;
    const int tx = tid & 15;
    const int ty = tid >> 4;

    float acc[8][8];
#pragma unroll
    for (int i = 0; i < 8; i++)
#pragma unroll
        for (int j = 0; j < 8; j++) acc[i][j] = 0.f;

    for (int k0 = 0; k0 < CDIM; k0 += 8) {
        float4 a4 = *(const float4*)(Ag + k0);
        float4 b4 = *(const float4*)(Bg + k0);
        As[lc + 0][lr] = a4.x; As[lc + 1][lr] = a4.y;
        As[lc + 2][lr] = a4.z; As[lc + 3][lr] = a4.w;
        Bs[lc + 0][lr] = b4.x; Bs[lc + 1][lr] = b4.y;
        Bs[lc + 2][lr] = b4.z; Bs[lc + 3][lr] = b4.w;
        __syncthreads();
#pragma unroll
        for (int kk = 0; kk < 8; kk++) {
            float af[8], bf[8];
            *(float4*)(af)     = *(const float4*)&As[kk][ty * 8];
            *(float4*)(af + 4) = *(const float4*)&As[kk][ty * 8 + 4];
            *(float4*)(bf)     = *(const float4*)&Bs[kk][tx * 8];
            *(float4*)(bf + 4) = *(const float4*)&Bs[kk][tx * 8 + 4];
#pragma unroll
            for (int i = 0; i < 8; i++)
#pragma unroll
                for (int j = 0; j < 8; j++) acc[i][j] += af[i] * bf[j];
        }
        __syncthreads();
    }

    float4 bb0 = *(const float4*)(bias + n0 + tx * 8);
    float4 bb1 = *(const float4*)(bias + n0 + tx * 8 + 4);
#pragma unroll
    for (int i = 0; i < 8; i++) {
        int m = m0 + ty * 8 + i;
        float* p = out + m * CDIM + n0 + tx * 8;
        float4 o0 = make_float4(acc[i][0] + bb0.x, acc[i][1] + bb0.y,
                                acc[i][2] + bb0.z, acc[i][3] + bb0.w);
        float4 o1 = make_float4(acc[i][4] + bb1.x, acc[i][5] + bb1.y,
                                acc[i][6] + bb1.z, acc[i][7] + bb1.w);
        *(float4*)p       = o0;
        *(float4*)(p + 4) = o1;
    }
}

// ---------------------------------------------------------------------------
extern "C" void kernel_launch(void* const* d_in, const int* in_sizes, int n_in,
                              void* d_out, int out_size) {
    const float* x      = (const float*)d_in[0];   // [4,4096,1024]
    const float* w_qkv  = (const float*)d_in[1];   // [3072,1024]
    const float* w_proj = (const float*)d_in[2];   // [1024,1024]
    const float* b_proj = (const float*)d_in[3];   // [1024]
    float* out = (float*)d_out;                    // [4,4096,1024]

    gemm_qkv<<<dim3(3 * CDIM / 128, MTOT / 128), 256>>>(x, w_qkv);
    kv_kernel<<<NBH, 256>>>();
    cudaFuncSetAttribute(attn_num_kernel,
                         cudaFuncAttributeMaxDynamicSharedMemorySize,
                         SMEM_NUM_BYTES);
    attn_num_kernel<<<dim3(NTOK / 128, NBH), 128, SMEM_NUM_BYTES>>>();
    gemm_proj<<<dim3(CDIM / 128, MTOT / 128), 256>>>(w_proj, b_proj, out);
}

// round 3
// speedup vs baseline: 2.7684x; 2.7684x over previous
#include <cuda_runtime.h>
#include <cuda_bf16.h>
#include <math.h>
#include <stdint.h>

#define NB    4
#define NTOK  4096
#define CDIM  1024
#define NH    16
#define HD    64
#define NBH   64
#define MTOT  16384
#define KDIM  1024
#define NQKV  3072

// GEMM tiling
#define BM 128
#define BN 128
#define BK 32
#define NCHUNK (KDIM / BK)      // 32
#define SAK 40                  // padded row stride (bf16 elems): 80B, 16B-aligned
#define TILE_BYTES (128 * SAK * 2)          // 10240
#define OFF_AHI 0
#define OFF_ALO (1 * TILE_BYTES)
#define OFF_BHI (2 * TILE_BYTES)
#define OFF_BLO (3 * TILE_BYTES)
#define STAGE_BYTES (4 * TILE_BYTES)        // 40960
#define SMEM_GEMM_BYTES (2 * STAGE_BYTES)   // 81920

// ---------------------------------------------------------------------------
// Scratch (device globals)
// ---------------------------------------------------------------------------
__device__ __nv_bfloat16 g_xhi[MTOT * KDIM];
__device__ __nv_bfloat16 g_xlo[MTOT * KDIM];
__device__ __nv_bfloat16 g_wqkv_hi[NQKV * KDIM];
__device__ __nv_bfloat16 g_wqkv_lo[NQKV * KDIM];
__device__ __nv_bfloat16 g_wproj_hi[CDIM * KDIM];
__device__ __nv_bfloat16 g_wproj_lo[CDIM * KDIM];
__device__ float g_q[NBH * NTOK * HD];
__device__ float g_k[NBH * NTOK * HD];
__device__ float g_v[NBH * NTOK * HD];
__device__ float g_kv_part[8 * NBH * HD * HD];
__device__ float g_ksum_part[8 * NBH * HD];
__device__ float g_kv[NBH * HD * HD];
__device__ float g_ksum[NBH * HD];
__device__ __nv_bfloat16 g_attn_hi[MTOT * CDIM];
__device__ __nv_bfloat16 g_attn_lo[MTOT * CDIM];

__device__ __forceinline__ float elu1(float x) {
    return x > 0.f ? x + 1.f : expf(x);
}

// ---------------------------------------------------------------------------
// PTX helpers (compute_103-safe: cp.async / ldmatrix / mma.sync only)
// ---------------------------------------------------------------------------
__device__ __forceinline__ uint32_t smem_u32(const void* p) {
    uint32_t a;
    asm("{ .reg .u64 t; cvta.to.shared.u64 t, %1; cvt.u32.u64 %0, t; }" : "=r"(a) : "l"(p));
    return a;
}
__device__ __forceinline__ void cp16(uint32_t s, const void* g) {
    asm volatile("cp.async.cg.shared.global [%0], [%1], 16;" :: "r"(s), "l"(g));
}
#define CP_COMMIT() asm volatile("cp.async.commit_group;" ::: "memory")
#define CP_WAIT1()  asm volatile("cp.async.wait_group 1;" ::: "memory")
#define CP_WAIT0()  asm volatile("cp.async.wait_group 0;" ::: "memory")

__device__ __forceinline__ void ldm4(uint32_t* r, uint32_t addr) {
    asm volatile("ldmatrix.sync.aligned.m8n8.x4.shared.b16 {%0,%1,%2,%3}, [%4];"
                 : "=r"(r[0]), "=r"(r[1]), "=r"(r[2]), "=r"(r[3]) : "r"(addr));
}
__device__ __forceinline__ void mma16816(float* d, const uint32_t* a,
                                         uint32_t b0, uint32_t b1) {
    asm volatile(
        "mma.sync.aligned.m16n8k16.row.col.f32.bf16.bf16.f32 "
        "{%0,%1,%2,%3}, {%4,%5,%6,%7}, {%8,%9}, {%0,%1,%2,%3};"
        : "+f"(d[0]), "+f"(d[1]), "+f"(d[2]), "+f"(d[3])
        : "r"(a[0]), "r"(a[1]), "r"(a[2]), "r"(a[3]), "r"(b0), "r"(b1));
}

// ---------------------------------------------------------------------------
// Shared mainloop: acc[2][8][4] += Ahi*Bhi + Alo*Bhi + Ahi*Blo over K=1024.
// ---------------------------------------------------------------------------
__device__ __forceinline__ void load_stage(
    uint32_t sbase,
    const __nv_bfloat16* __restrict__ Ahi, const __nv_bfloat16* __restrict__ Alo,
    const __nv_bfloat16* __restrict__ Bhi, const __nv_bfloat16* __restrict__ Blo,
    int m0, int n0, int kc, int tid)
{
#pragma unroll
    for (int t = 0; t < 2; t++) {
        int chunk = t * 256 + tid;
        int row = chunk >> 2;
        int c8 = (chunk & 3) * 8;
        uint32_t so = (uint32_t)(row * SAK + c8) * 2;
        size_t ga = (size_t)(m0 + row) * KDIM + kc + c8;
        size_t gb = (size_t)(n0 + row) * KDIM + kc + c8;
        cp16(sbase + OFF_AHI + so, Ahi + ga);
        cp16(sbase + OFF_ALO + so, Alo + ga);
        cp16(sbase + OFF_BHI + so, Bhi + gb);
        cp16(sbase + OFF_BLO + so, Blo + gb);
    }
}

__device__ __forceinline__ void mma_mainloop(
    const __nv_bfloat16* __restrict__ Ahi, const __nv_bfloat16* __restrict__ Alo,
    const __nv_bfloat16* __restrict__ Bhi, const __nv_bfloat16* __restrict__ Blo,
    int m0, int n0, uint32_t sm32, float acc[2][8][4])
{
    const int tid = threadIdx.x;
    const int lane = tid & 31;
    const int wid = tid >> 5;
    const int wm = wid & 3;        // 4 warps over M
    const int wn = wid >> 2;       // 2 warps over N

    load_stage(sm32, Ahi, Alo, Bhi, Blo, m0, n0, 0, tid);
    CP_COMMIT();
    load_stage(sm32 + STAGE_BYTES, Ahi, Alo, Bhi, Blo, m0, n0, BK, tid);
    CP_COMMIT();

    // per-thread ldmatrix row/col offsets (in elements)
    const int a_row = (lane & 15);
    const int a_koff = (lane & 16) ? 8 : 0;
    const int b_row = (lane & 7) + ((lane & 16) >> 1);
    const int b_koff = (lane & 8) ? 8 : 0;

    for (int c = 0; c < NCHUNK; c++) {
        if (c == NCHUNK - 1) CP_WAIT0(); else CP_WAIT1();
        __syncthreads();

        const uint32_t sb = sm32 + (c & 1) * STAGE_BYTES;
#pragma unroll
        for (int kk = 0; kk < BK; kk += 16) {
            uint32_t ah[2][4], al[2][4], bb[4][4];
#pragma unroll
            for (int ma = 0; ma < 2; ma++) {
                uint32_t off = (uint32_t)((wm * 32 + ma * 16 + a_row) * SAK +
                                          kk + a_koff) * 2;
                ldm4(ah[ma], sb + OFF_AHI + off);
                ldm4(al[ma], sb + OFF_ALO + off);
            }
#pragma unroll
            for (int nb = 0; nb < 4; nb++) {
                uint32_t off = (uint32_t)((wn * 64 + nb * 16 + b_row) * SAK +
                                          kk + b_koff) * 2;
                ldm4(bb[nb], sb + OFF_BHI + off);
            }
#pragma unroll
            for (int ma = 0; ma < 2; ma++)
#pragma unroll
                for (int na = 0; na < 8; na++)
                    mma16816(acc[ma][na], ah[ma],
                             bb[na >> 1][(na & 1) * 2], bb[na >> 1][(na & 1) * 2 + 1]);
#pragma unroll
            for (int ma = 0; ma < 2; ma++)
#pragma unroll
                for (int na = 0; na < 8; na++)
                    mma16816(acc[ma][na], al[ma],
                             bb[na >> 1][(na & 1) * 2], bb[na >> 1][(na & 1) * 2 + 1]);
#pragma unroll
            for (int nb = 0; nb < 4; nb++) {
                uint32_t off = (uint32_t)((wn * 64 + nb * 16 + b_row) * SAK +
                                          kk + b_koff) * 2;
                ldm4(bb[nb], sb + OFF_BLO + off);
            }
#pragma unroll
            for (int ma = 0; ma < 2; ma++)
#pragma unroll
                for (int na = 0; na < 8; na++)
                    mma16816(acc[ma][na], ah[ma],
                             bb[na >> 1][(na & 1) * 2], bb[na >> 1][(na & 1) * 2 + 1]);
        }
        __syncthreads();
        if (c + 2 < NCHUNK) {
            load_stage(sb, Ahi, Alo, Bhi, Blo, m0, n0, (c + 2) * BK, tid);
            CP_COMMIT();
        }
    }
}

// ---------------------------------------------------------------------------
// QKV GEMM: D = x @ w_qkv^T; epilogue: elu+1 for q,k; per-head scatter.
// ---------------------------------------------------------------------------
__global__ __launch_bounds__(256, 2) void gemm_qkv_mma() {
    extern __shared__ char smem[];
    const uint32_t sm32 = smem_u32(smem);
    const int m0 = blockIdx.y * BM;
    const int n0 = blockIdx.x * BN;

    float acc[2][8][4];
#pragma unroll
    for (int i = 0; i < 2; i++)
#pragma unroll
        for (int j = 0; j < 8; j++)
#pragma unroll
            for (int k = 0; k < 4; k++) acc[i][j][k] = 0.f;

    mma_mainloop(g_xhi, g_xlo, g_wqkv_hi, g_wqkv_lo, m0, n0, sm32, acc);

    const int tid = threadIdx.x;
    const int lane = tid & 31;
    const int wid = tid >> 5;
    const int wm = wid & 3, wn = wid >> 2;
    const int r0 = lane >> 2;
    const int c0 = (lane & 3) * 2;

#pragma unroll
    for (int ma = 0; ma < 2; ma++) {
#pragma unroll
        for (int na = 0; na < 8; na++) {
            const int colg = n0 + wn * 64 + na * 8 + c0;
            const int part = colg >> 10;
            const int h = (colg & 1023) >> 6;
            const int d = colg & 63;
            float* dst = (part == 0) ? g_q : (part == 1) ? g_k : g_v;
            const bool feat = part < 2;
#pragma unroll
            for (int hf = 0; hf < 2; hf++) {
                const int m = m0 + wm * 32 + ma * 16 + r0 + hf * 8;
                const int b = m >> 12, t = m & 4095;
                float v0 = acc[ma][na][hf * 2 + 0];
                float v1 = acc[ma][na][hf * 2 + 1];
                if (feat) { v0 = elu1(v0); v1 = elu1(v1); }
                float2 o = make_float2(v0, v1);
                *(float2*)(dst + ((size_t)(b * NH + h) * NTOK + t) * HD + d) = o;
            }
        }
    }
}

// ---------------------------------------------------------------------------
// Proj GEMM: out = attn @ w_proj^T + bias
// ---------------------------------------------------------------------------
__global__ __launch_bounds__(256, 2) void gemm_proj_mma(const float* __restrict__ bias,
                                                        float* __restrict__ out) {
    extern __shared__ char smem[];
    const uint32_t sm32 = smem_u32(smem);
    const int m0 = blockIdx.y * BM;
    const int n0 = blockIdx.x * BN;

    float acc[2][8][4];
#pragma unroll
    for (int i = 0; i < 2; i++)
#pragma unroll
        for (int j = 0; j < 8; j++)
#pragma unroll
            for (int k = 0; k < 4; k++) acc[i][j][k] = 0.f;

    mma_mainloop(g_attn_hi, g_attn_lo, g_wproj_hi, g_wproj_lo, m0, n0, sm32, acc);

    const int tid = threadIdx.x;
    const int lane = tid & 31;
    const int wid = tid >> 5;
    const int wm = wid & 3, wn = wid >> 2;
    const int r0 = lane >> 2;
    const int c0 = (lane & 3) * 2;

#pragma unroll
    for (int ma = 0; ma < 2; ma++) {
#pragma unroll
        for (int na = 0; na < 8; na++) {
            const int colg = n0 + wn * 64 + na * 8 + c0;
            const float b0 = bias[colg], b1 = bias[colg + 1];
#pragma unroll
            for (int hf = 0; hf < 2; hf++) {
                const int m = m0 + wm * 32 + ma * 16 + r0 + hf * 8;
                float2 o = make_float2(acc[ma][na][hf * 2 + 0] + b0,
                                       acc[ma][na][hf * 2 + 1] + b1);
                *(float2*)(out + (size_t)m * CDIM + colg) = o;
            }
        }
    }
}

// ---------------------------------------------------------------------------
// fp32 -> bf16 hi/lo split. which: 0=x, 1=w_qkv, 2=w_proj
// ---------------------------------------------------------------------------
__global__ void split_kernel(const float* __restrict__ in, int which, int n) {
    __nv_bfloat16* hi = (which == 0) ? g_xhi : (which == 1) ? g_wqkv_hi : g_wproj_hi;
    __nv_bfloat16* lo = (which == 0) ? g_xlo : (which == 1) ? g_wqkv_lo : g_wproj_lo;
    int i = (blockIdx.x * blockDim.x + threadIdx.x) * 4;
    if (i >= n) return;
    float4 v = *(const float4*)(in + i);
    float vv[4] = {v.x, v.y, v.z, v.w};
    __nv_bfloat16 h[4], l[4];
#pragma unroll
    for (int j = 0; j < 4; j++) {
        h[j] = __float2bfloat16(vv[j]);
        l[j] = __float2bfloat16(vv[j] - __bfloat162float(h[j]));
    }
    __nv_bfloat162 h01, h23, l01, l23;
    h01.x = h[0]; h01.y = h[1]; h23.x = h[2]; h23.y = h[3];
    l01.x = l[0]; l01.y = l[1]; l23.x = l[2]; l23.y = l[3];
    *(__nv_bfloat162*)(hi + i)     = h01;
    *(__nv_bfloat162*)(hi + i + 2) = h23;
    *(__nv_bfloat162*)(lo + i)     = l01;
    *(__nv_bfloat162*)(lo + i + 2) = l23;
}

// ---------------------------------------------------------------------------
// kv partials: per (bh, split of 512 tokens): kv[d][e], ksum[d]
// ---------------------------------------------------------------------------
__global__ __launch_bounds__(256) void kv_part_kernel() {
    __shared__ __align__(16) float ks[32][64];
    __shared__ __align__(16) float vs[32][64];
    const int tid = threadIdx.x;
    const int bh = blockIdx.x >> 3;
    const int sp = blockIdx.x & 7;
    const float* kp = g_k + (size_t)bh * NTOK * HD;
    const float* vp = g_v + (size_t)bh * NTOK * HD;
    const int lrow = tid >> 3;
    const int lcol = (tid & 7) * 8;
    const int tx = tid & 15, ty = tid >> 4;
    const int e0 = tx * 4, d0 = ty * 4;

    float acc[4][4];
#pragma unroll
    for (int i = 0; i < 4; i++)
#pragma unroll
        for (int j = 0; j < 4; j++) acc[i][j] = 0.f;
    float ksacc = 0.f;

    const int nbeg = sp * 512;
    for (int n0 = nbeg; n0 < nbeg + 512; n0 += 32) {
        __syncthreads();
        const float* kr = kp + (size_t)(n0 + lrow) * HD + lcol;
        const float* vr = vp + (size_t)(n0 + lrow) * HD + lcol;
        *(float4*)&ks[lrow][lcol]     = *(const float4*)kr;
        *(float4*)&ks[lrow][lcol + 4] = *(const float4*)(kr + 4);
        *(float4*)&vs[lrow][lcol]     = *(const float4*)vr;
        *(float4*)&vs[lrow][lcol + 4] = *(const float4*)(vr + 4);
        __syncthreads();
#pragma unroll 4
        for (int nn = 0; nn < 32; nn++) {
            float kf[4], vf[4];
            *(float4*)kf = *(const float4*)&ks[nn][d0];
            *(float4*)vf = *(const float4*)&vs[nn][e0];
#pragma unroll
            for (int i = 0; i < 4; i++)
#pragma unroll
                for (int j = 0; j < 4; j++) acc[i][j] += kf[i] * vf[j];
        }
        if (tid < 64) {
#pragma unroll 4
            for (int nn = 0; nn < 32; nn++) ksacc += ks[nn][tid];
        }
    }

    float* kvout = g_kv_part + (size_t)(sp * NBH + bh) * (HD * HD);
#pragma unroll
    for (int i = 0; i < 4; i++)
        *(float4*)(kvout + (d0 + i) * HD + e0) =
            make_float4(acc[i][0], acc[i][1], acc[i][2], acc[i][3]);
    if (tid < 64) g_ksum_part[(sp * NBH + bh) * HD + tid] = ksacc;
}

__global__ void kv_reduce_kernel() {
    const int bh = blockIdx.x;
    const int tid = threadIdx.x;
    for (int j = tid; j < HD * HD; j += 256) {
        float s = 0.f;
#pragma unroll
        for (int p = 0; p < 8; p++) s += g_kv_part[(size_t)(p * NBH + bh) * (HD * HD) + j];
        g_kv[(size_t)bh * HD * HD + j] = s;
    }
    if (tid < HD) {
        float s = 0.f;
#pragma unroll
        for (int p = 0; p < 8; p++) s += g_ksum_part[(p * NBH + bh) * HD + tid];
        g_ksum[bh * HD + tid] = s;
    }
}

// ---------------------------------------------------------------------------
// attn numerator + normalize; writes bf16 hi/lo for the proj GEMM.
// ---------------------------------------------------------------------------
#define QT_STRIDE 129
#define SMEM_NUM_BYTES ((64 * QT_STRIDE + 64 * 64 + 64) * 4)

__global__ __launch_bounds__(128) void attn_num_kernel() {
    extern __shared__ float sm[];
    float* qt  = sm;
    float* kvs = sm + 64 * QT_STRIDE;
    float* kss = kvs + 64 * 64;
    const int tid = threadIdx.x;
    const int bh = blockIdx.y;
    const int b = bh >> 4, h = bh & 15;
    const int row0 = blockIdx.x * 128;
    const float* qp  = g_q + ((size_t)bh * NTOK + row0) * HD;
    const float* kvp = g_kv + (size_t)bh * HD * HD;

#pragma unroll
    for (int c = 0; c < 8; c++) {
        int g = (c * 128 + tid) * 4;
        *(float4*)&kvs[g] = *(const float4*)(kvp + g);
    }
    if (tid < 64) kss[tid] = g_ksum[bh * HD + tid];
#pragma unroll
    for (int c = 0; c < 16; c++) {
        int f = c * 128 + tid;
        float4 qv = *(const float4*)(qp + f * 4);
        int row = f >> 4;
        int col = (f & 15) * 4;
        qt[(col + 0) * QT_STRIDE + row] = qv.x;
        qt[(col + 1) * QT_STRIDE + row] = qv.y;
        qt[(col + 2) * QT_STRIDE + row] = qv.z;
        qt[(col + 3) * QT_STRIDE + row] = qv.w;
    }
    __syncthreads();

    float acc[64];
#pragma unroll
    for (int e = 0; e < 64; e++) acc[e] = 0.f;
    float qk = 0.f;
#pragma unroll 4
    for (int d = 0; d < 64; d++) {
        float qd = qt[d * QT_STRIDE + tid];
        qk += qd * kss[d];
        const float4* kr = (const float4*)&kvs[d * 64];
#pragma unroll
        for (int e4 = 0; e4 < 16; e4++) {
            float4 kv4 = kr[e4];
            acc[e4 * 4 + 0] += qd * kv4.x;
            acc[e4 * 4 + 1] += qd * kv4.y;
            acc[e4 * 4 + 2] += qd * kv4.z;
            acc[e4 * 4 + 3] += qd * kv4.w;
        }
    }

    const float inv = 1.f / (qk + 1e-8f);
    const size_t obase = ((size_t)(b * NTOK + row0 + tid)) * CDIM + h * HD;
    __nv_bfloat16* ph = g_attn_hi + obase;
    __nv_bfloat16* pl = g_attn_lo + obase;
#pragma unroll
    for (int e2 = 0; e2 < 32; e2++) {
        float o0 = acc[2 * e2 + 0] * inv;
        float o1 = acc[2 * e2 + 1] * inv;
        __nv_bfloat16 h0 = __float2bfloat16(o0);
        __nv_bfloat16 h1 = __float2bfloat16(o1);
        __nv_bfloat162 hh; hh.x = h0; hh.y = h1;
        __nv_bfloat162 ll;
        ll.x = __float2bfloat16(o0 - __bfloat162float(h0));
        ll.y = __float2bfloat16(o1 - __bfloat162float(h1));
        *(__nv_bfloat162*)(ph + 2 * e2) = hh;
        *(__nv_bfloat162*)(pl + 2 * e2) = ll;
    }
}

// ---------------------------------------------------------------------------
extern "C" void kernel_launch(void* const* d_in, const int* in_sizes, int n_in,
                              void* d_out, int out_size) {
    const float* x      = (const float*)d_in[0];
    const float* w_qkv  = (const float*)d_in[1];
    const float* w_proj = (const float*)d_in[2];
    const float* b_proj = (const float*)d_in[3];
    float* out = (float*)d_out;

    cudaFuncSetAttribute(gemm_qkv_mma, cudaFuncAttributeMaxDynamicSharedMemorySize,
                         SMEM_GEMM_BYTES);
    cudaFuncSetAttribute(gemm_proj_mma, cudaFuncAttributeMaxDynamicSharedMemorySize,
                         SMEM_GEMM_BYTES);
    cudaFuncSetAttribute(attn_num_kernel, cudaFuncAttributeMaxDynamicSharedMemorySize,
                         SMEM_NUM_BYTES);

    split_kernel<<<(MTOT * KDIM) / 1024, 256>>>(x, 0, MTOT * KDIM);
    split_kernel<<<(NQKV * KDIM) / 1024, 256>>>(w_qkv, 1, NQKV * KDIM);
    split_kernel<<<(CDIM * KDIM) / 1024, 256>>>(w_proj, 2, CDIM * KDIM);

    gemm_qkv_mma<<<dim3(NQKV / BN, MTOT / BM), 256, SMEM_GEMM_BYTES>>>();

    kv_part_kernel<<<NBH * 8, 256>>>();
    kv_reduce_kernel<<<NBH, 256>>>();

    attn_num_kernel<<<dim3(NTOK / 128, NBH), 128, SMEM_NUM_BYTES>>>();

    gemm_proj_mma<<<dim3(CDIM / BN, MTOT / BM), 256, SMEM_GEMM_BYTES>>>(b_proj, out);
}

// round 4
// speedup vs baseline: 3.1655x; 1.1434x over previous
#include <cuda_runtime.h>
#include <cuda_bf16.h>
#include <math.h>
#include <stdint.h>

#define NB    4
#define NTOK  4096
#define CDIM  1024
#define NH    16
#define HD    64
#define NBH   64
#define MTOT  16384
#define KDIM  1024
#define NQKV  3072

// GEMM tiling
#define BM 128
#define BN 128
#define BK 32
#define NCHUNK (KDIM / BK)      // 32
#define NSTAGE 3
// swizzled tile: 128 rows x 64 bytes (32 bf16), no padding
#define TILE_BYTES (128 * 64)               // 8192
#define OFF_AHI 0
#define OFF_ALO (1 * TILE_BYTES)
#define OFF_BHI (2 * TILE_BYTES)
#define OFF_BLO (3 * TILE_BYTES)
#define STAGE_BYTES (4 * TILE_BYTES)        // 32768
#define SMEM_GEMM_BYTES (NSTAGE * STAGE_BYTES)  // 98304

// bank swizzle for 64B rows: XOR bits[4:7) with row (bits[6:9) of offset)
#define SWZ(o) ((o) ^ ((((o) >> 6) & 7) << 4))

// ---------------------------------------------------------------------------
// Scratch (device globals)
// ---------------------------------------------------------------------------
__device__ __nv_bfloat16 g_xhi[MTOT * KDIM];
__device__ __nv_bfloat16 g_xlo[MTOT * KDIM];
__device__ __nv_bfloat16 g_wqkv_hi[NQKV * KDIM];
__device__ __nv_bfloat16 g_wqkv_lo[NQKV * KDIM];
__device__ __nv_bfloat16 g_wproj_hi[CDIM * KDIM];
__device__ __nv_bfloat16 g_wproj_lo[CDIM * KDIM];
__device__ float g_q[NBH * NTOK * HD];
__device__ float g_k[NBH * NTOK * HD];
__device__ float g_v[NBH * NTOK * HD];
__device__ float g_kv_part[8 * NBH * HD * HD];
__device__ float g_ksum_part[8 * NBH * HD];
__device__ float g_kv[NBH * HD * HD];
__device__ float g_ksum[NBH * HD];
__device__ __nv_bfloat16 g_attn_hi[MTOT * CDIM];
__device__ __nv_bfloat16 g_attn_lo[MTOT * CDIM];

__device__ __forceinline__ float elu1(float x) {
    return x > 0.f ? x + 1.f : expf(x);
}

// ---------------------------------------------------------------------------
// PTX helpers (compute_103-safe: cp.async / ldmatrix / mma.sync only)
// ---------------------------------------------------------------------------
__device__ __forceinline__ uint32_t smem_u32(const void* p) {
    uint32_t a;
    asm("{ .reg .u64 t; cvta.to.shared.u64 t, %1; cvt.u32.u64 %0, t; }" : "=r"(a) : "l"(p));
    return a;
}
__device__ __forceinline__ void cp16(uint32_t s, const void* g) {
    asm volatile("cp.async.cg.shared.global [%0], [%1], 16;" :: "r"(s), "l"(g));
}
#define CP_COMMIT() asm volatile("cp.async.commit_group;" ::: "memory")
#define CP_WAIT1()  asm volatile("cp.async.wait_group 1;" ::: "memory")
#define CP_WAIT0()  asm volatile("cp.async.wait_group 0;" ::: "memory")

__device__ __forceinline__ void ldm4(uint32_t* r, uint32_t addr) {
    asm volatile("ldmatrix.sync.aligned.m8n8.x4.shared.b16 {%0,%1,%2,%3}, [%4];"
                 : "=r"(r[0]), "=r"(r[1]), "=r"(r[2]), "=r"(r[3]) : "r"(addr));
}
__device__ __forceinline__ void mma16816(float* d, const uint32_t* a,
                                         uint32_t b0, uint32_t b1) {
    asm volatile(
        "mma.sync.aligned.m16n8k16.row.col.f32.bf16.bf16.f32 "
        "{%0,%1,%2,%3}, {%4,%5,%6,%7}, {%8,%9}, {%0,%1,%2,%3};"
        : "+f"(d[0]), "+f"(d[1]), "+f"(d[2]), "+f"(d[3])
        : "r"(a[0]), "r"(a[1]), "r"(a[2]), "r"(a[3]), "r"(b0), "r"(b1));
}

// ---------------------------------------------------------------------------
// Stage loader: 4 tiles of 128x32 bf16, swizzled 64B rows.
// ---------------------------------------------------------------------------
__device__ __forceinline__ void load_stage(
    uint32_t sbase,
    const __nv_bfloat16* __restrict__ Ahi, const __nv_bfloat16* __restrict__ Alo,
    const __nv_bfloat16* __restrict__ Bhi, const __nv_bfloat16* __restrict__ Blo,
    int m0, int n0, int kc, int tid)
{
#pragma unroll
    for (int t = 0; t < 2; t++) {
        int idx = t * 256 + tid;
        int row = idx >> 2;
        int c16 = idx & 3;
        uint32_t so = SWZ((uint32_t)(row * 64 + c16 * 16));
        size_t ga = (size_t)(m0 + row) * KDIM + kc + c16 * 8;
        size_t gb = (size_t)(n0 + row) * KDIM + kc + c16 * 8;
        cp16(sbase + OFF_AHI + so, Ahi + ga);
        cp16(sbase + OFF_ALO + so, Alo + ga);
        cp16(sbase + OFF_BHI + so, Bhi + gb);
        cp16(sbase + OFF_BLO + so, Blo + gb);
    }
}

// ---------------------------------------------------------------------------
// Mainloop: acc[2][8][4] += Ahi*Bhi + Alo*Bhi + Ahi*Blo over K=1024.
// 3-stage cp.async pipeline, single __syncthreads per chunk.
// ---------------------------------------------------------------------------
__device__ __forceinline__ void mma_mainloop(
    const __nv_bfloat16* __restrict__ Ahi, const __nv_bfloat16* __restrict__ Alo,
    const __nv_bfloat16* __restrict__ Bhi, const __nv_bfloat16* __restrict__ Blo,
    int m0, int n0, uint32_t sm32, float acc[2][8][4])
{
    const int tid = threadIdx.x;
    const int lane = tid & 31;
    const int wid = tid >> 5;
    const int wm = wid & 3;        // 4 warps over M
    const int wn = wid >> 2;       // 2 warps over N

    load_stage(sm32, Ahi, Alo, Bhi, Blo, m0, n0, 0, tid);
    CP_COMMIT();
    load_stage(sm32 + STAGE_BYTES, Ahi, Alo, Bhi, Blo, m0, n0, BK, tid);
    CP_COMMIT();

    const int a_row = (lane & 15);
    const int a_koff = (lane & 16) ? 8 : 0;
    const int b_row = (lane & 7) + ((lane & 16) >> 1);
    const int b_koff = (lane & 8) ? 8 : 0;

    int cur = 0, pre = 2;
    for (int c = 0; c < NCHUNK; c++) {
        if (c == NCHUNK - 1) CP_WAIT0(); else CP_WAIT1();
        __syncthreads();

        if (c + 2 < NCHUNK) {
            load_stage(sm32 + pre * STAGE_BYTES, Ahi, Alo, Bhi, Blo,
                       m0, n0, (c + 2) * BK, tid);
            CP_COMMIT();
        }

        const uint32_t sb = sm32 + cur * STAGE_BYTES;
#pragma unroll
        for (int kk = 0; kk < BK; kk += 16) {
            uint32_t ah[2][4], al[2][4], bb[4][4];
#pragma unroll
            for (int ma = 0; ma < 2; ma++) {
                uint32_t off = SWZ((uint32_t)((wm * 32 + ma * 16 + a_row) * 64 +
                                              (kk + a_koff) * 2));
                ldm4(ah[ma], sb + OFF_AHI + off);
                ldm4(al[ma], sb + OFF_ALO + off);
            }
#pragma unroll
            for (int nb = 0; nb < 4; nb++) {
                uint32_t off = SWZ((uint32_t)((wn * 64 + nb * 16 + b_row) * 64 +
                                              (kk + b_koff) * 2));
                ldm4(bb[nb], sb + OFF_BHI + off);
            }
#pragma unroll
            for (int ma = 0; ma < 2; ma++)
#pragma unroll
                for (int na = 0; na < 8; na++)
                    mma16816(acc[ma][na], ah[ma],
                             bb[na >> 1][(na & 1) * 2], bb[na >> 1][(na & 1) * 2 + 1]);
#pragma unroll
            for (int ma = 0; ma < 2; ma++)
#pragma unroll
                for (int na = 0; na < 8; na++)
                    mma16816(acc[ma][na], al[ma],
                             bb[na >> 1][(na & 1) * 2], bb[na >> 1][(na & 1) * 2 + 1]);
#pragma unroll
            for (int nb = 0; nb < 4; nb++) {
                uint32_t off = SWZ((uint32_t)((wn * 64 + nb * 16 + b_row) * 64 +
                                              (kk + b_koff) * 2));
                ldm4(bb[nb], sb + OFF_BLO + off);
            }
#pragma unroll
            for (int ma = 0; ma < 2; ma++)
#pragma unroll
                for (int na = 0; na < 8; na++)
                    mma16816(acc[ma][na], ah[ma],
                             bb[na >> 1][(na & 1) * 2], bb[na >> 1][(na & 1) * 2 + 1]);
        }
        cur = (cur == NSTAGE - 1) ? 0 : cur + 1;
        pre = (pre == NSTAGE - 1) ? 0 : pre + 1;
    }
}

// ---------------------------------------------------------------------------
// QKV GEMM: D = x @ w_qkv^T; epilogue: elu+1 for q,k; per-head scatter.
// ---------------------------------------------------------------------------
__global__ __launch_bounds__(256, 2) void gemm_qkv_mma() {
    extern __shared__ char smem[];
    const uint32_t sm32 = smem_u32(smem);
    const int m0 = blockIdx.y * BM;
    const int n0 = blockIdx.x * BN;

    float acc[2][8][4];
#pragma unroll
    for (int i = 0; i < 2; i++)
#pragma unroll
        for (int j = 0; j < 8; j++)
#pragma unroll
            for (int k = 0; k < 4; k++) acc[i][j][k] = 0.f;

    mma_mainloop(g_xhi, g_xlo, g_wqkv_hi, g_wqkv_lo, m0, n0, sm32, acc);

    const int tid = threadIdx.x;
    const int lane = tid & 31;
    const int wid = tid >> 5;
    const int wm = wid & 3, wn = wid >> 2;
    const int r0 = lane >> 2;
    const int c0 = (lane & 3) * 2;

#pragma unroll
    for (int ma = 0; ma < 2; ma++) {
#pragma unroll
        for (int na = 0; na < 8; na++) {
            const int colg = n0 + wn * 64 + na * 8 + c0;
            const int part = colg >> 10;
            const int h = (colg & 1023) >> 6;
            const int d = colg & 63;
            float* dst = (part == 0) ? g_q : (part == 1) ? g_k : g_v;
            const bool feat = part < 2;
#pragma unroll
            for (int hf = 0; hf < 2; hf++) {
                const int m = m0 + wm * 32 + ma * 16 + r0 + hf * 8;
                const int b = m >> 12, t = m & 4095;
                float v0 = acc[ma][na][hf * 2 + 0];
                float v1 = acc[ma][na][hf * 2 + 1];
                if (feat) { v0 = elu1(v0); v1 = elu1(v1); }
                float2 o = make_float2(v0, v1);
                *(float2*)(dst + ((size_t)(b * NH + h) * NTOK + t) * HD + d) = o;
            }
        }
    }
}

// ---------------------------------------------------------------------------
// Proj GEMM: out = attn @ w_proj^T + bias
// ---------------------------------------------------------------------------
__global__ __launch_bounds__(256, 2) void gemm_proj_mma(const float* __restrict__ bias,
                                                        float* __restrict__ out) {
    extern __shared__ char smem[];
    const uint32_t sm32 = smem_u32(smem);
    const int m0 = blockIdx.y * BM;
    const int n0 = blockIdx.x * BN;

    float acc[2][8][4];
#pragma unroll
    for (int i = 0; i < 2; i++)
#pragma unroll
        for (int j = 0; j < 8; j++)
#pragma unroll
            for (int k = 0; k < 4; k++) acc[i][j][k] = 0.f;

    mma_mainloop(g_attn_hi, g_attn_lo, g_wproj_hi, g_wproj_lo, m0, n0, sm32, acc);

    const int tid = threadIdx.x;
    const int lane = tid & 31;
    const int wid = tid >> 5;
    const int wm = wid & 3, wn = wid >> 2;
    const int r0 = lane >> 2;
    const int c0 = (lane & 3) * 2;

#pragma unroll
    for (int ma = 0; ma < 2; ma++) {
#pragma unroll
        for (int na = 0; na < 8; na++) {
            const int colg = n0 + wn * 64 + na * 8 + c0;
            const float b0 = bias[colg], b1 = bias[colg + 1];
#pragma unroll
            for (int hf = 0; hf < 2; hf++) {
                const int m = m0 + wm * 32 + ma * 16 + r0 + hf * 8;
                float2 o = make_float2(acc[ma][na][hf * 2 + 0] + b0,
                                       acc[ma][na][hf * 2 + 1] + b1);
                *(float2*)(out + (size_t)m * CDIM + colg) = o;
            }
        }
    }
}

// ---------------------------------------------------------------------------
// fp32 -> bf16 hi/lo split. which: 0=x, 1=w_qkv, 2=w_proj
// ---------------------------------------------------------------------------
__global__ void split_kernel(const float* __restrict__ in, int which, int n) {
    __nv_bfloat16* hi = (which == 0) ? g_xhi : (which == 1) ? g_wqkv_hi : g_wproj_hi;
    __nv_bfloat16* lo = (which == 0) ? g_xlo : (which == 1) ? g_wqkv_lo : g_wproj_lo;
    int i = (blockIdx.x * blockDim.x + threadIdx.x) * 4;
    if (i >= n) return;
    float4 v = *(const float4*)(in + i);
    float vv[4] = {v.x, v.y, v.z, v.w};
    __nv_bfloat16 h[4], l[4];
#pragma unroll
    for (int j = 0; j < 4; j++) {
        h[j] = __float2bfloat16(vv[j]);
        l[j] = __float2bfloat16(vv[j] - __bfloat162float(h[j]));
    }
    __nv_bfloat162 h01, h23, l01, l23;
    h01.x = h[0]; h01.y = h[1]; h23.x = h[2]; h23.y = h[3];
    l01.x = l[0]; l01.y = l[1]; l23.x = l[2]; l23.y = l[3];
    *(__nv_bfloat162*)(hi + i)     = h01;
    *(__nv_bfloat162*)(hi + i + 2) = h23;
    *(__nv_bfloat162*)(lo + i)     = l01;
    *(__nv_bfloat162*)(lo + i + 2) = l23;
}

// ---------------------------------------------------------------------------
// kv partials: per (bh, split of 512 tokens): kv[d][e], ksum[d]
// ---------------------------------------------------------------------------
__global__ __launch_bounds__(256) void kv_part_kernel() {
    __shared__ __align__(16) float ks[32][64];
    __shared__ __align__(16) float vs[32][64];
    const int tid = threadIdx.x;
    const int bh = blockIdx.x >> 3;
    const int sp = blockIdx.x & 7;
    const float* kp = g_k + (size_t)bh * NTOK * HD;
    const float* vp = g_v + (size_t)bh * NTOK * HD;
    const int lrow = tid >> 3;
    const int lcol = (tid & 7) * 8;
    const int tx = tid & 15, ty = tid >> 4;
    const int e0 = tx * 4, d0 = ty * 4;

    float acc[4][4];
#pragma unroll
    for (int i = 0; i < 4; i++)
#pragma unroll
        for (int j = 0; j < 4; j++) acc[i][j] = 0.f;
    float ksacc = 0.f;

    const int nbeg = sp * 512;
    for (int n0 = nbeg; n0 < nbeg + 512; n0 += 32) {
        __syncthreads();
        const float* kr = kp + (size_t)(n0 + lrow) * HD + lcol;
        const float* vr = vp + (size_t)(n0 + lrow) * HD + lcol;
        *(float4*)&ks[lrow][lcol]     = *(const float4*)kr;
        *(float4*)&ks[lrow][lcol + 4] = *(const float4*)(kr + 4);
        *(float4*)&vs[lrow][lcol]     = *(const float4*)vr;
        *(float4*)&vs[lrow][lcol + 4] = *(const float4*)(vr + 4);
        __syncthreads();
#pragma unroll 4
        for (int nn = 0; nn < 32; nn++) {
            float kf[4], vf[4];
            *(float4*)kf = *(const float4*)&ks[nn][d0];
            *(float4*)vf = *(const float4*)&vs[nn][e0];
#pragma unroll
            for (int i = 0; i < 4; i++)
#pragma unroll
                for (int j = 0; j < 4; j++) acc[i][j] += kf[i] * vf[j];
        }
        if (tid < 64) {
#pragma unroll 4
            for (int nn = 0; nn < 32; nn++) ksacc += ks[nn][tid];
        }
    }

    float* kvout = g_kv_part + (size_t)(sp * NBH + bh) * (HD * HD);
#pragma unroll
    for (int i = 0; i < 4; i++)
        *(float4*)(kvout + (d0 + i) * HD + e0) =
            make_float4(acc[i][0], acc[i][1], acc[i][2], acc[i][3]);
    if (tid < 64) g_ksum_part[(sp * NBH + bh) * HD + tid] = ksacc;
}

__global__ void kv_reduce_kernel() {
    const int bh = blockIdx.x;
    const int tid = threadIdx.x;
    for (int j = tid; j < HD * HD; j += 256) {
        float s = 0.f;
#pragma unroll
        for (int p = 0; p < 8; p++) s += g_kv_part[(size_t)(p * NBH + bh) * (HD * HD) + j];
        g_kv[(size_t)bh * HD * HD + j] = s;
    }
    if (tid < HD) {
        float s = 0.f;
#pragma unroll
        for (int p = 0; p < 8; p++) s += g_ksum_part[(p * NBH + bh) * HD + tid];
        g_ksum[bh * HD + tid] = s;
    }
}

// ---------------------------------------------------------------------------
// attn numerator + normalize; writes bf16 hi/lo for the proj GEMM.
// ---------------------------------------------------------------------------
#define QT_STRIDE 129
#define SMEM_NUM_BYTES ((64 * QT_STRIDE + 64 * 64 + 64) * 4)

__global__ __launch_bounds__(128) void attn_num_kernel() {
    extern __shared__ float sm[];
    float* qt  = sm;
    float* kvs = sm + 64 * QT_STRIDE;
    float* kss = kvs + 64 * 64;
    const int tid = threadIdx.x;
    const int bh = blockIdx.y;
    const int b = bh >> 4, h = bh & 15;
    const int row0 = blockIdx.x * 128;
    const float* qp  = g_q + ((size_t)bh * NTOK + row0) * HD;
    const float* kvp = g_kv + (size_t)bh * HD * HD;

#pragma unroll
    for (int c = 0; c < 8; c++) {
        int g = (c * 128 + tid) * 4;
        *(float4*)&kvs[g] = *(const float4*)(kvp + g);
    }
    if (tid < 64) kss[tid] = g_ksum[bh * HD + tid];
#pragma unroll
    for (int c = 0; c < 16; c++) {
        int f = c * 128 + tid;
        float4 qv = *(const float4*)(qp + f * 4);
        int row = f >> 4;
        int col = (f & 15) * 4;
        qt[(col + 0) * QT_STRIDE + row] = qv.x;
        qt[(col + 1) * QT_STRIDE + row] = qv.y;
        qt[(col + 2) * QT_STRIDE + row] = qv.z;
        qt[(col + 3) * QT_STRIDE + row] = qv.w;
    }
    __syncthreads();

    float acc[64];
#pragma unroll
    for (int e = 0; e < 64; e++) acc[e] = 0.f;
    float qk = 0.f;
#pragma unroll 4
    for (int d = 0; d < 64; d++) {
        float qd = qt[d * QT_STRIDE + tid];
        qk += qd * kss[d];
        const float4* kr = (const float4*)&kvs[d * 64];
#pragma unroll
        for (int e4 = 0; e4 < 16; e4++) {
            float4 kv4 = kr[e4];
            acc[e4 * 4 + 0] += qd * kv4.x;
            acc[e4 * 4 + 1] += qd * kv4.y;
            acc[e4 * 4 + 2] += qd * kv4.z;
            acc[e4 * 4 + 3] += qd * kv4.w;
        }
    }

    const float inv = 1.f / (qk + 1e-8f);
    const size_t obase = ((size_t)(b * NTOK + row0 + tid)) * CDIM + h * HD;
    __nv_bfloat16* ph = g_attn_hi + obase;
    __nv_bfloat16* pl = g_attn_lo + obase;
#pragma unroll
    for (int e2 = 0; e2 < 32; e2++) {
        float o0 = acc[2 * e2 + 0] * inv;
        float o1 = acc[2 * e2 + 1] * inv;
        __nv_bfloat16 h0 = __float2bfloat16(o0);
        __nv_bfloat16 h1 = __float2bfloat16(o1);
        __nv_bfloat162 hh; hh.x = h0; hh.y = h1;
        __nv_bfloat162 ll;
        ll.x = __float2bfloat16(o0 - __bfloat162float(h0));
        ll.y = __float2bfloat16(o1 - __bfloat162float(h1));
        *(__nv_bfloat162*)(ph + 2 * e2) = hh;
        *(__nv_bfloat162*)(pl + 2 * e2) = ll;
    }
}

// ---------------------------------------------------------------------------
extern "C" void kernel_launch(void* const* d_in, const int* in_sizes, int n_in,
                              void* d_out, int out_size) {
    const float* x      = (const float*)d_in[0];
    const float* w_qkv  = (const float*)d_in[1];
    const float* w_proj = (const float*)d_in[2];
    const float* b_proj = (const float*)d_in[3];
    float* out = (float*)d_out;

    cudaFuncSetAttribute(gemm_qkv_mma, cudaFuncAttributeMaxDynamicSharedMemorySize,
                         SMEM_GEMM_BYTES);
    cudaFuncSetAttribute(gemm_proj_mma, cudaFuncAttributeMaxDynamicSharedMemorySize,
                         SMEM_GEMM_BYTES);
    cudaFuncSetAttribute(attn_num_kernel, cudaFuncAttributeMaxDynamicSharedMemorySize,
                         SMEM_NUM_BYTES);

    split_kernel<<<(MTOT * KDIM) / 1024, 256>>>(x, 0, MTOT * KDIM);
    split_kernel<<<(NQKV * KDIM) / 1024, 256>>>(w_qkv, 1, NQKV * KDIM);
    split_kernel<<<(CDIM * KDIM) / 1024, 256>>>(w_proj, 2, CDIM * KDIM);

    gemm_qkv_mma<<<dim3(NQKV / BN, MTOT / BM), 256, SMEM_GEMM_BYTES>>>();

    kv_part_kernel<<<NBH * 8, 256>>>();
    kv_reduce_kernel<<<NBH, 256>>>();

    attn_num_kernel<<<dim3(NTOK / 128, NBH), 128, SMEM_NUM_BYTES>>>();

    gemm_proj_mma<<<dim3(CDIM / BN, MTOT / BM), 256, SMEM_GEMM_BYTES>>>(b_proj, out);
}

// round 5
// speedup vs baseline: 4.1312x; 1.3051x over previous
#include <cuda_runtime.h>
#include <cuda_fp16.h>
#include <math.h>
#include <stdint.h>

#define NB    4
#define NTOK  4096
#define CDIM  1024
#define NH    16
#define HD    64
#define NBH   64
#define MTOT  16384
#define KDIM  1024
#define NQKV  3072

// GEMM tiling
#define BM 128
#define BN 128
#define BK 32
#define NCHUNK (KDIM / BK)      // 32
#define NSTAGE 4
// swizzled tile: 128 rows x 64 bytes (32 fp16), no padding
#define TILE_BYTES (128 * 64)               // 8192
#define OFF_AHI 0
#define OFF_ALO (1 * TILE_BYTES)
#define OFF_B   (2 * TILE_BYTES)
#define STAGE_BYTES (3 * TILE_BYTES)        // 24576
#define SMEM_GEMM_BYTES (NSTAGE * STAGE_BYTES)  // 98304

// bank swizzle for 64B rows: XOR bits[4:7) with row bits[6:9)
#define SWZ(o) ((o) ^ ((((o) >> 6) & 7) << 4))

// ---------------------------------------------------------------------------
// Scratch (device globals)
// ---------------------------------------------------------------------------
__device__ __half g_xhi[MTOT * KDIM];
__device__ __half g_xlo[MTOT * KDIM];
__device__ __half g_wqkv[NQKV * KDIM];
__device__ __half g_wproj[CDIM * KDIM];
__device__ float g_q[NBH * NTOK * HD];
__device__ float g_k[NBH * NTOK * HD];
__device__ float g_v[NBH * NTOK * HD];
__device__ float g_kv_part[8 * NBH * HD * HD];
__device__ float g_ksum_part[8 * NBH * HD];
__device__ float g_kv[NBH * HD * HD];
__device__ float g_ksum[NBH * HD];
__device__ __half g_attn_hi[MTOT * CDIM];
__device__ __half g_attn_lo[MTOT * CDIM];

__device__ __forceinline__ float elu1(float x) {
    return x > 0.f ? x + 1.f : expf(x);
}

// ---------------------------------------------------------------------------
// PTX helpers (compute_103-safe: cp.async / ldmatrix / mma.sync only)
// ---------------------------------------------------------------------------
__device__ __forceinline__ uint32_t smem_u32(const void* p) {
    uint32_t a;
    asm("{ .reg .u64 t; cvta.to.shared.u64 t, %1; cvt.u32.u64 %0, t; }" : "=r"(a) : "l"(p));
    return a;
}
__device__ __forceinline__ void cp16(uint32_t s, const void* g) {
    asm volatile("cp.async.cg.shared.global [%0], [%1], 16;" :: "r"(s), "l"(g));
}
#define CP_COMMIT() asm volatile("cp.async.commit_group;" ::: "memory")
#define CP_WAIT2()  asm volatile("cp.async.wait_group 2;" ::: "memory")
#define CP_WAIT1()  asm volatile("cp.async.wait_group 1;" ::: "memory")
#define CP_WAIT0()  asm volatile("cp.async.wait_group 0;" ::: "memory")

__device__ __forceinline__ void ldm4(uint32_t* r, uint32_t addr) {
    asm volatile("ldmatrix.sync.aligned.m8n8.x4.shared.b16 {%0,%1,%2,%3}, [%4];"
                 : "=r"(r[0]), "=r"(r[1]), "=r"(r[2]), "=r"(r[3]) : "r"(addr));
}
__device__ __forceinline__ void mma16816(float* d, const uint32_t* a,
                                         uint32_t b0, uint32_t b1) {
    asm volatile(
        "mma.sync.aligned.m16n8k16.row.col.f32.f16.f16.f32 "
        "{%0,%1,%2,%3}, {%4,%5,%6,%7}, {%8,%9}, {%0,%1,%2,%3};"
        : "+f"(d[0]), "+f"(d[1]), "+f"(d[2]), "+f"(d[3])
        : "r"(a[0]), "r"(a[1]), "r"(a[2]), "r"(a[3]), "r"(b0), "r"(b1));
}

// ---------------------------------------------------------------------------
// Stage loader: 3 tiles (A-hi, A-lo, B) of 128x32 fp16, swizzled 64B rows.
// 6 cp.async x 16B per thread.
// ---------------------------------------------------------------------------
__device__ __forceinline__ void load_stage(
    uint32_t sbase,
    const __half* __restrict__ Ahi, const __half* __restrict__ Alo,
    const __half* __restrict__ B,
    int m0, int n0, int kc, int tid)
{
#pragma unroll
    for (int t = 0; t < 2; t++) {
        int idx = t * 256 + tid;
        int row = idx >> 2;
        int c16 = idx & 3;
        uint32_t so = SWZ((uint32_t)(row * 64 + c16 * 16));
        size_t ga = (size_t)(m0 + row) * KDIM + kc + c16 * 8;
        size_t gb = (size_t)(n0 + row) * KDIM + kc + c16 * 8;
        cp16(sbase + OFF_AHI + so, Ahi + ga);
        cp16(sbase + OFF_ALO + so, Alo + ga);
        cp16(sbase + OFF_B + so, B + gb);
    }
}

// ---------------------------------------------------------------------------
// Mainloop: acc[2][8][4] += Ahi*B + Alo*B over K=1024.
// 4-stage cp.async pipeline, single __syncthreads per chunk.
// ---------------------------------------------------------------------------
__device__ __forceinline__ void mma_mainloop(
    const __half* __restrict__ Ahi, const __half* __restrict__ Alo,
    const __half* __restrict__ B,
    int m0, int n0, uint32_t sm32, float acc[2][8][4])
{
    const int tid = threadIdx.x;
    const int lane = tid & 31;
    const int wid = tid >> 5;
    const int wm = wid & 3;        // 4 warps over M
    const int wn = wid >> 2;       // 2 warps over N

    load_stage(sm32, Ahi, Alo, B, m0, n0, 0, tid);
    CP_COMMIT();
    load_stage(sm32 + STAGE_BYTES, Ahi, Alo, B, m0, n0, BK, tid);
    CP_COMMIT();
    load_stage(sm32 + 2 * STAGE_BYTES, Ahi, Alo, B, m0, n0, 2 * BK, tid);
    CP_COMMIT();

    const int a_row = (lane & 15);
    const int a_koff = (lane & 16) ? 8 : 0;
    const int b_row = (lane & 7) + ((lane & 16) >> 1);
    const int b_koff = (lane & 8) ? 8 : 0;

    for (int c = 0; c < NCHUNK; c++) {
        if (c < NCHUNK - 2) CP_WAIT2();
        else if (c == NCHUNK - 2) CP_WAIT1();
        else CP_WAIT0();
        __syncthreads();

        if (c + 3 < NCHUNK) {
            load_stage(sm32 + ((c + 3) & 3) * STAGE_BYTES, Ahi, Alo, B,
                       m0, n0, (c + 3) * BK, tid);
            CP_COMMIT();
        }

        const uint32_t sb = sm32 + (c & 3) * STAGE_BYTES;
#pragma unroll
        for (int kk = 0; kk < BK; kk += 16) {
            uint32_t ah[2][4], al[2][4], bb[4][4];
#pragma unroll
            for (int ma = 0; ma < 2; ma++) {
                uint32_t off = SWZ((uint32_t)((wm * 32 + ma * 16 + a_row) * 64 +
                                              (kk + a_koff) * 2));
                ldm4(ah[ma], sb + OFF_AHI + off);
                ldm4(al[ma], sb + OFF_ALO + off);
            }
#pragma unroll
            for (int nb = 0; nb < 4; nb++) {
                uint32_t off = SWZ((uint32_t)((wn * 64 + nb * 16 + b_row) * 64 +
                                              (kk + b_koff) * 2));
                ldm4(bb[nb], sb + OFF_B + off);
            }
#pragma unroll
            for (int ma = 0; ma < 2; ma++)
#pragma unroll
                for (int na = 0; na < 8; na++)
                    mma16816(acc[ma][na], ah[ma],
                             bb[na >> 1][(na & 1) * 2], bb[na >> 1][(na & 1) * 2 + 1]);
#pragma unroll
            for (int ma = 0; ma < 2; ma++)
#pragma unroll
                for (int na = 0; na < 8; na++)
                    mma16816(acc[ma][na], al[ma],
                             bb[na >> 1][(na & 1) * 2], bb[na >> 1][(na & 1) * 2 + 1]);
        }
    }
}

// ---------------------------------------------------------------------------
// QKV GEMM: D = x @ w_qkv^T; epilogue: elu+1 for q,k; per-head scatter.
// ---------------------------------------------------------------------------
__global__ __launch_bounds__(256, 2) void gemm_qkv_mma() {
    extern __shared__ char smem[];
    const uint32_t sm32 = smem_u32(smem);
    const int m0 = blockIdx.y * BM;
    const int n0 = blockIdx.x * BN;

    float acc[2][8][4];
#pragma unroll
    for (int i = 0; i < 2; i++)
#pragma unroll
        for (int j = 0; j < 8; j++)
#pragma unroll
            for (int k = 0; k < 4; k++) acc[i][j][k] = 0.f;

    mma_mainloop(g_xhi, g_xlo, g_wqkv, m0, n0, sm32, acc);

    const int tid = threadIdx.x;
    const int lane = tid & 31;
    const int wid = tid >> 5;
    const int wm = wid & 3, wn = wid >> 2;
    const int r0 = lane >> 2;
    const int c0 = (lane & 3) * 2;

#pragma unroll
    for (int ma = 0; ma < 2; ma++) {
#pragma unroll
        for (int na = 0; na < 8; na++) {
            const int colg = n0 + wn * 64 + na * 8 + c0;
            const int part = colg >> 10;
            const int h = (colg & 1023) >> 6;
            const int d = colg & 63;
            float* dst = (part == 0) ? g_q : (part == 1) ? g_k : g_v;
            const bool feat = part < 2;
#pragma unroll
            for (int hf = 0; hf < 2; hf++) {
                const int m = m0 + wm * 32 + ma * 16 + r0 + hf * 8;
                const int b = m >> 12, t = m & 4095;
                float v0 = acc[ma][na][hf * 2 + 0];
                float v1 = acc[ma][na][hf * 2 + 1];
                if (feat) { v0 = elu1(v0); v1 = elu1(v1); }
                float2 o = make_float2(v0, v1);
                *(float2*)(dst + ((size_t)(b * NH + h) * NTOK + t) * HD + d) = o;
            }
        }
    }
}

// ---------------------------------------------------------------------------
// Proj GEMM: out = attn @ w_proj^T + bias
// ---------------------------------------------------------------------------
__global__ __launch_bounds__(256, 2) void gemm_proj_mma(const float* __restrict__ bias,
                                                        float* __restrict__ out) {
    extern __shared__ char smem[];
    const uint32_t sm32 = smem_u32(smem);
    const int m0 = blockIdx.y * BM;
    const int n0 = blockIdx.x * BN;

    float acc[2][8][4];
#pragma unroll
    for (int i = 0; i < 2; i++)
#pragma unroll
        for (int j = 0; j < 8; j++)
#pragma unroll
            for (int k = 0; k < 4; k++) acc[i][j][k] = 0.f;

    mma_mainloop(g_attn_hi, g_attn_lo, g_wproj, m0, n0, sm32, acc);

    const int tid = threadIdx.x;
    const int lane = tid & 31;
    const int wid = tid >> 5;
    const int wm = wid & 3, wn = wid >> 2;
    const int r0 = lane >> 2;
    const int c0 = (lane & 3) * 2;

#pragma unroll
    for (int ma = 0; ma < 2; ma++) {
#pragma unroll
        for (int na = 0; na < 8; na++) {
            const int colg = n0 + wn * 64 + na * 8 + c0;
            const float b0 = bias[colg], b1 = bias[colg + 1];
#pragma unroll
            for (int hf = 0; hf < 2; hf++) {
                const int m = m0 + wm * 32 + ma * 16 + r0 + hf * 8;
                float2 o = make_float2(acc[ma][na][hf * 2 + 0] + b0,
                                       acc[ma][na][hf * 2 + 1] + b1);
                *(float2*)(out + (size_t)m * CDIM + colg) = o;
            }
        }
    }
}

// ---------------------------------------------------------------------------
// fp32 -> fp16 hi/lo split for x
// ---------------------------------------------------------------------------
__global__ void split_x_kernel(const float* __restrict__ in, int n) {
    int i = (blockIdx.x * blockDim.x + threadIdx.x) * 4;
    if (i >= n) return;
    float4 v = *(const float4*)(in + i);
    float vv[4] = {v.x, v.y, v.z, v.w};
    __half h[4], l[4];
#pragma unroll
    for (int j = 0; j < 4; j++) {
        h[j] = __float2half_rn(vv[j]);
        l[j] = __float2half_rn(vv[j] - __half2float(h[j]));
    }
    __half2 h01 = __halves2half2(h[0], h[1]);
    __half2 h23 = __halves2half2(h[2], h[3]);
    __half2 l01 = __halves2half2(l[0], l[1]);
    __half2 l23 = __halves2half2(l[2], l[3]);
    *(__half2*)(g_xhi + i)     = h01;
    *(__half2*)(g_xhi + i + 2) = h23;
    *(__half2*)(g_xlo + i)     = l01;
    *(__half2*)(g_xlo + i + 2) = l23;
}

// fp32 -> fp16 convert for weights. which: 0 = w_qkv, 1 = w_proj
__global__ void conv_w_kernel(const float* __restrict__ in, int which, int n) {
    __half* dst = (which == 0) ? g_wqkv : g_wproj;
    int i = (blockIdx.x * blockDim.x + threadIdx.x) * 4;
    if (i >= n) return;
    float4 v = *(const float4*)(in + i);
    __half2 o01 = __halves2half2(__float2half_rn(v.x), __float2half_rn(v.y));
    __half2 o23 = __halves2half2(__float2half_rn(v.z), __float2half_rn(v.w));
    *(__half2*)(dst + i)     = o01;
    *(__half2*)(dst + i + 2) = o23;
}

// ---------------------------------------------------------------------------
// kv partials: per (bh, split of 512 tokens): kv[d][e], ksum[d]
// ---------------------------------------------------------------------------
__global__ __launch_bounds__(256) void kv_part_kernel() {
    __shared__ __align__(16) float ks[32][64];
    __shared__ __align__(16) float vs[32][64];
    const int tid = threadIdx.x;
    const int bh = blockIdx.x >> 3;
    const int sp = blockIdx.x & 7;
    const float* kp = g_k + (size_t)bh * NTOK * HD;
    const float* vp = g_v + (size_t)bh * NTOK * HD;
    const int lrow = tid >> 3;
    const int lcol = (tid & 7) * 8;
    const int tx = tid & 15, ty = tid >> 4;
    const int e0 = tx * 4, d0 = ty * 4;

    float acc[4][4];
#pragma unroll
    for (int i = 0; i < 4; i++)
#pragma unroll
        for (int j = 0; j < 4; j++) acc[i][j] = 0.f;
    float ksacc = 0.f;

    const int nbeg = sp * 512;
    for (int n0 = nbeg; n0 < nbeg + 512; n0 += 32) {
        __syncthreads();
        const float* kr = kp + (size_t)(n0 + lrow) * HD + lcol;
        const float* vr = vp + (size_t)(n0 + lrow) * HD + lcol;
        *(float4*)&ks[lrow][lcol]     = *(const float4*)kr;
        *(float4*)&ks[lrow][lcol + 4] = *(const float4*)(kr + 4);
        *(float4*)&vs[lrow][lcol]     = *(const float4*)vr;
        *(float4*)&vs[lrow][lcol + 4] = *(const float4*)(vr + 4);
        __syncthreads();
#pragma unroll 4
        for (int nn = 0; nn < 32; nn++) {
            float kf[4], vf[4];
            *(float4*)kf = *(const float4*)&ks[nn][d0];
            *(float4*)vf = *(const float4*)&vs[nn][e0];
#pragma unroll
            for (int i = 0; i < 4; i++)
#pragma unroll
                for (int j = 0; j < 4; j++) acc[i][j] += kf[i] * vf[j];
        }
        if (tid < 64) {
#pragma unroll 4
            for (int nn = 0; nn < 32; nn++) ksacc += ks[nn][tid];
        }
    }

    float* kvout = g_kv_part + (size_t)(sp * NBH + bh) * (HD * HD);
#pragma unroll
    for (int i = 0; i < 4; i++)
        *(float4*)(kvout + (d0 + i) * HD + e0) =
            make_float4(acc[i][0], acc[i][1], acc[i][2], acc[i][3]);
    if (tid < 64) g_ksum_part[(sp * NBH + bh) * HD + tid] = ksacc;
}

__global__ void kv_reduce_kernel() {
    const int bh = blockIdx.x;
    const int tid = threadIdx.x;
    for (int j = tid; j < HD * HD; j += 256) {
        float s = 0.f;
#pragma unroll
        for (int p = 0; p < 8; p++) s += g_kv_part[(size_t)(p * NBH + bh) * (HD * HD) + j];
        g_kv[(size_t)bh * HD * HD + j] = s;
    }
    if (tid < HD) {
        float s = 0.f;
#pragma unroll
        for (int p = 0; p < 8; p++) s += g_ksum_part[(p * NBH + bh) * HD + tid];
        g_ksum[bh * HD + tid] = s;
    }
}

// ---------------------------------------------------------------------------
// attn numerator + normalize; writes fp16 hi/lo for the proj GEMM.
// ---------------------------------------------------------------------------
#define QT_STRIDE 129
#define SMEM_NUM_BYTES ((64 * QT_STRIDE + 64 * 64 + 64) * 4)

__global__ __launch_bounds__(128) void attn_num_kernel() {
    extern __shared__ float sm[];
    float* qt  = sm;
    float* kvs = sm + 64 * QT_STRIDE;
    float* kss = kvs + 64 * 64;
    const int tid = threadIdx.x;
    const int bh = blockIdx.y;
    const int b = bh >> 4, h = bh & 15;
    const int row0 = blockIdx.x * 128;
    const float* qp  = g_q + ((size_t)bh * NTOK + row0) * HD;
    const float* kvp = g_kv + (size_t)bh * HD * HD;

#pragma unroll
    for (int c = 0; c < 8; c++) {
        int g = (c * 128 + tid) * 4;
        *(float4*)&kvs[g] = *(const float4*)(kvp + g);
    }
    if (tid < 64) kss[tid] = g_ksum[bh * HD + tid];
#pragma unroll
    for (int c = 0; c < 16; c++) {
        int f = c * 128 + tid;
        float4 qv = *(const float4*)(qp + f * 4);
        int row = f >> 4;
        int col = (f & 15) * 4;
        qt[(col + 0) * QT_STRIDE + row] = qv.x;
        qt[(col + 1) * QT_STRIDE + row] = qv.y;
        qt[(col + 2) * QT_STRIDE + row] = qv.z;
        qt[(col + 3) * QT_STRIDE + row] = qv.w;
    }
    __syncthreads();

    float acc[64];
#pragma unroll
    for (int e = 0; e < 64; e++) acc[e] = 0.f;
    float qk = 0.f;
#pragma unroll 4
    for (int d = 0; d < 64; d++) {
        float qd = qt[d * QT_STRIDE + tid];
        qk += qd * kss[d];
        const float4* kr = (const float4*)&kvs[d * 64];
#pragma unroll
        for (int e4 = 0; e4 < 16; e4++) {
            float4 kv4 = kr[e4];
            acc[e4 * 4 + 0] += qd * kv4.x;
            acc[e4 * 4 + 1] += qd * kv4.y;
            acc[e4 * 4 + 2] += qd * kv4.z;
            acc[e4 * 4 + 3] += qd * kv4.w;
        }
    }

    const float inv = 1.f / (qk + 1e-8f);
    const size_t obase = ((size_t)(b * NTOK + row0 + tid)) * CDIM + h * HD;
    __half* ph = g_attn_hi + obase;
    __half* pl = g_attn_lo + obase;
#pragma unroll
    for (int e2 = 0; e2 < 32; e2++) {
        float o0 = acc[2 * e2 + 0] * inv;
        float o1 = acc[2 * e2 + 1] * inv;
        __half h0 = __float2half_rn(o0);
        __half h1 = __float2half_rn(o1);
        __half l0 = __float2half_rn(o0 - __half2float(h0));
        __half l1 = __float2half_rn(o1 - __half2float(h1));
        *(__half2*)(ph + 2 * e2) = __halves2half2(h0, h1);
        *(__half2*)(pl + 2 * e2) = __halves2half2(l0, l1);
    }
}

// ---------------------------------------------------------------------------
extern "C" void kernel_launch(void* const* d_in, const int* in_sizes, int n_in,
                              void* d_out, int out_size) {
    const float* x      = (const float*)d_in[0];
    const float* w_qkv  = (const float*)d_in[1];
    const float* w_proj = (const float*)d_in[2];
    const float* b_proj = (const float*)d_in[3];
    float* out = (float*)d_out;

    cudaFuncSetAttribute(gemm_qkv_mma, cudaFuncAttributeMaxDynamicSharedMemorySize,
                         SMEM_GEMM_BYTES);
    cudaFuncSetAttribute(gemm_proj_mma, cudaFuncAttributeMaxDynamicSharedMemorySize,
                         SMEM_GEMM_BYTES);
    cudaFuncSetAttribute(attn_num_kernel, cudaFuncAttributeMaxDynamicSharedMemorySize,
                         SMEM_NUM_BYTES);

    split_x_kernel<<<(MTOT * KDIM) / 1024, 256>>>(x, MTOT * KDIM);
    conv_w_kernel<<<(NQKV * KDIM) / 1024, 256>>>(w_qkv, 0, NQKV * KDIM);
    conv_w_kernel<<<(CDIM * KDIM) / 1024, 256>>>(w_proj, 1, CDIM * KDIM);

    gemm_qkv_mma<<<dim3(NQKV / BN, MTOT / BM), 256, SMEM_GEMM_BYTES>>>();

    kv_part_kernel<<<NBH * 8, 256>>>();
    kv_reduce_kernel<<<NBH, 256>>>();

    attn_num_kernel<<<dim3(NTOK / 128, NBH), 128, SMEM_NUM_BYTES>>>();

    gemm_proj_mma<<<dim3(CDIM / BN, MTOT / BM), 256, SMEM_GEMM_BYTES>>>(b_proj, out);
}

// round 6
// speedup vs baseline: 4.2254x; 1.0228x over previous
#include <cuda_runtime.h>
#include <cuda_fp16.h>
#include <math.h>
#include <stdint.h>

#define NB    4
#define NTOK  4096
#define CDIM  1024
#define NH    16
#define HD    64
#define NBH   64
#define MTOT  16384
#define KDIM  1024
#define NQKV  3072

// GEMM tiling
#define BM 128
#define BN 128
#define BK 64
#define NCHUNK (KDIM / BK)      // 16
// tile: 128 rows x 128 bytes (64 fp16), SW128 swizzle
#define TILE_BYTES (128 * 128)              // 16384
#define OFF_AHI 0
#define OFF_ALO (1 * TILE_BYTES)
#define OFF_B   (2 * TILE_BYTES)
#define STAGE_BYTES (3 * TILE_BYTES)        // 49152
#define SMEM_GEMM_BYTES (2 * STAGE_BYTES)   // 98304

// SW128 swizzle: XOR bits[4:7) with row bits[7:10)
#define SWZ(o) ((o) ^ (((o) >> 3) & 0x70))

#define KVSPLIT 16

// ---------------------------------------------------------------------------
// Scratch (device globals)
// ---------------------------------------------------------------------------
__device__ __half g_xhi[MTOT * KDIM];
__device__ __half g_xlo[MTOT * KDIM];
__device__ __half g_wqkv[NQKV * KDIM];
__device__ __half g_wproj[CDIM * KDIM];
__device__ float g_q[NBH * NTOK * HD];
__device__ float g_k[NBH * NTOK * HD];
__device__ float g_v[NBH * NTOK * HD];
__device__ float g_kv_part[KVSPLIT * NBH * HD * HD];
__device__ float g_ksum_part[KVSPLIT * NBH * HD];
__device__ float g_kv[NBH * HD * HD];
__device__ float g_ksum[NBH * HD];
__device__ __half g_attn_hi[MTOT * CDIM];
__device__ __half g_attn_lo[MTOT * CDIM];

__device__ __forceinline__ float elu1(float x) {
    return x > 0.f ? x + 1.f : expf(x);
}

// ---------------------------------------------------------------------------
// PTX helpers (compute_103-safe)
// ---------------------------------------------------------------------------
__device__ __forceinline__ uint32_t smem_u32(const void* p) {
    uint32_t a;
    asm("{ .reg .u64 t; cvta.to.shared.u64 t, %1; cvt.u32.u64 %0, t; }" : "=r"(a) : "l"(p));
    return a;
}
__device__ __forceinline__ void cp16(uint32_t s, const void* g) {
    asm volatile("cp.async.cg.shared.global [%0], [%1], 16;" :: "r"(s), "l"(g));
}
#define CP_COMMIT() asm volatile("cp.async.commit_group;" ::: "memory")
#define CP_WAIT0()  asm volatile("cp.async.wait_group 0;" ::: "memory")

__device__ __forceinline__ void ldm4(uint32_t* r, uint32_t addr) {
    asm volatile("ldmatrix.sync.aligned.m8n8.x4.shared.b16 {%0,%1,%2,%3}, [%4];"
                 : "=r"(r[0]), "=r"(r[1]), "=r"(r[2]), "=r"(r[3]) : "r"(addr));
}
__device__ __forceinline__ void mma16816(float* d, const uint32_t* a,
                                         uint32_t b0, uint32_t b1) {
    asm volatile(
        "mma.sync.aligned.m16n8k16.row.col.f32.f16.f16.f32 "
        "{%0,%1,%2,%3}, {%4,%5,%6,%7}, {%8,%9}, {%0,%1,%2,%3};"
        : "+f"(d[0]), "+f"(d[1]), "+f"(d[2]), "+f"(d[3])
        : "r"(a[0]), "r"(a[1]), "r"(a[2]), "r"(a[3]), "r"(b0), "r"(b1));
}

// ---------------------------------------------------------------------------
// Stage loader: 3 tiles (A-hi, A-lo, B) of 128x64 fp16, SW128 rows.
// 12 cp.async x 16B per thread.
// ---------------------------------------------------------------------------
__device__ __forceinline__ void load_stage(
    uint32_t sbase,
    const __half* __restrict__ Ahi, const __half* __restrict__ Alo,
    const __half* __restrict__ B,
    int m0, int n0, int kc, int tid)
{
#pragma unroll
    for (int t = 0; t < 4; t++) {
        int idx = t * 256 + tid;
        int row = idx >> 3;
        int c16 = idx & 7;
        uint32_t so = SWZ((uint32_t)(row * 128 + c16 * 16));
        size_t ga = (size_t)(m0 + row) * KDIM + kc + c16 * 8;
        size_t gb = (size_t)(n0 + row) * KDIM + kc + c16 * 8;
        cp16(sbase + OFF_AHI + so, Ahi + ga);
        cp16(sbase + OFF_ALO + so, Alo + ga);
        cp16(sbase + OFF_B + so, B + gb);
    }
}

// ---------------------------------------------------------------------------
// Mainloop: acc[2][8][4] += Ahi*B + Alo*B over K=1024.
// 2-stage double buffer, BK=64, one __syncthreads per chunk.
// ---------------------------------------------------------------------------
__device__ __forceinline__ void mma_mainloop(
    const __half* __restrict__ Ahi, const __half* __restrict__ Alo,
    const __half* __restrict__ B,
    int m0, int n0, uint32_t sm32, float acc[2][8][4])
{
    const int tid = threadIdx.x;
    const int lane = tid & 31;
    const int wid = tid >> 5;
    const int wm = wid & 3;        // 4 warps over M
    const int wn = wid >> 2;       // 2 warps over N

    load_stage(sm32, Ahi, Alo, B, m0, n0, 0, tid);
    CP_COMMIT();

    const int a_row = (lane & 15);
    const int a_koff = (lane & 16) ? 8 : 0;
    const int b_row = (lane & 7) + ((lane & 16) >> 1);
    const int b_koff = (lane & 8) ? 8 : 0;

    // linear (pre-swizzle) byte offsets within a tile
    const uint32_t aoff0 = (uint32_t)((wm * 32 + a_row) * 128 + a_koff * 2);
    const uint32_t aoff1 = aoff0 + 16 * 128;
    uint32_t boffs[4];
#pragma unroll
    for (int nb = 0; nb < 4; nb++)
        boffs[nb] = (uint32_t)((wn * 64 + nb * 16 + b_row) * 128 + b_koff * 2);

    for (int c = 0; c < NCHUNK; c++) {
        CP_WAIT0();
        __syncthreads();

        if (c + 1 < NCHUNK) {
            load_stage(sm32 + ((c + 1) & 1) * STAGE_BYTES, Ahi, Alo, B,
                       m0, n0, (c + 1) * BK, tid);
            CP_COMMIT();
        }

        const uint32_t sb = sm32 + (c & 1) * STAGE_BYTES;
#pragma unroll
        for (int kk = 0; kk < BK; kk += 16) {
            uint32_t ah[2][4], al[2][4], bb[4][4];
            const uint32_t kb = (uint32_t)(kk * 2);
            ldm4(ah[0], sb + OFF_AHI + SWZ(aoff0 + kb));
            ldm4(ah[1], sb + OFF_AHI + SWZ(aoff1 + kb));
            ldm4(al[0], sb + OFF_ALO + SWZ(aoff0 + kb));
            ldm4(al[1], sb + OFF_ALO + SWZ(aoff1 + kb));
#pragma unroll
            for (int nb = 0; nb < 4; nb++)
                ldm4(bb[nb], sb + OFF_B + SWZ(boffs[nb] + kb));
#pragma unroll
            for (int ma = 0; ma < 2; ma++)
#pragma unroll
                for (int na = 0; na < 8; na++)
                    mma16816(acc[ma][na], ah[ma],
                             bb[na >> 1][(na & 1) * 2], bb[na >> 1][(na & 1) * 2 + 1]);
#pragma unroll
            for (int ma = 0; ma < 2; ma++)
#pragma unroll
                for (int na = 0; na < 8; na++)
                    mma16816(acc[ma][na], al[ma],
                             bb[na >> 1][(na & 1) * 2], bb[na >> 1][(na & 1) * 2 + 1]);
        }
    }
}

// ---------------------------------------------------------------------------
// QKV GEMM: D = x @ w_qkv^T; epilogue: elu+1 for q,k; per-head scatter.
// ---------------------------------------------------------------------------
__global__ __launch_bounds__(256, 2) void gemm_qkv_mma() {
    extern __shared__ char smem[];
    const uint32_t sm32 = smem_u32(smem);
    const int m0 = blockIdx.y * BM;
    const int n0 = blockIdx.x * BN;

    float acc[2][8][4];
#pragma unroll
    for (int i = 0; i < 2; i++)
#pragma unroll
        for (int j = 0; j < 8; j++)
#pragma unroll
            for (int k = 0; k < 4; k++) acc[i][j][k] = 0.f;

    mma_mainloop(g_xhi, g_xlo, g_wqkv, m0, n0, sm32, acc);

    const int tid = threadIdx.x;
    const int lane = tid & 31;
    const int wid = tid >> 5;
    const int wm = wid & 3, wn = wid >> 2;
    const int r0 = lane >> 2;
    const int c0 = (lane & 3) * 2;

#pragma unroll
    for (int ma = 0; ma < 2; ma++) {
#pragma unroll
        for (int na = 0; na < 8; na++) {
            const int colg = n0 + wn * 64 + na * 8 + c0;
            const int part = colg >> 10;
            const int h = (colg & 1023) >> 6;
            const int d = colg & 63;
            float* dst = (part == 0) ? g_q : (part == 1) ? g_k : g_v;
            const bool feat = part < 2;
#pragma unroll
            for (int hf = 0; hf < 2; hf++) {
                const int m = m0 + wm * 32 + ma * 16 + r0 + hf * 8;
                const int b = m >> 12, t = m & 4095;
                float v0 = acc[ma][na][hf * 2 + 0];
                float v1 = acc[ma][na][hf * 2 + 1];
                if (feat) { v0 = elu1(v0); v1 = elu1(v1); }
                float2 o = make_float2(v0, v1);
                *(float2*)(dst + ((size_t)(b * NH + h) * NTOK + t) * HD + d) = o;
            }
        }
    }
}

// ---------------------------------------------------------------------------
// Proj GEMM: out = attn @ w_proj^T + bias
// ---------------------------------------------------------------------------
__global__ __launch_bounds__(256, 2) void gemm_proj_mma(const float* __restrict__ bias,
                                                        float* __restrict__ out) {
    extern __shared__ char smem[];
    const uint32_t sm32 = smem_u32(smem);
    const int m0 = blockIdx.y * BM;
    const int n0 = blockIdx.x * BN;

    float acc[2][8][4];
#pragma unroll
    for (int i = 0; i < 2; i++)
#pragma unroll
        for (int j = 0; j < 8; j++)
#pragma unroll
            for (int k = 0; k < 4; k++) acc[i][j][k] = 0.f;

    mma_mainloop(g_attn_hi, g_attn_lo, g_wproj, m0, n0, sm32, acc);

    const int tid = threadIdx.x;
    const int lane = tid & 31;
    const int wid = tid >> 5;
    const int wm = wid & 3, wn = wid >> 2;
    const int r0 = lane >> 2;
    const int c0 = (lane & 3) * 2;

#pragma unroll
    for (int ma = 0; ma < 2; ma++) {
#pragma unroll
        for (int na = 0; na < 8; na++) {
            const int colg = n0 + wn * 64 + na * 8 + c0;
            const float b0 = bias[colg], b1 = bias[colg + 1];
#pragma unroll
            for (int hf = 0; hf < 2; hf++) {
                const int m = m0 + wm * 32 + ma * 16 + r0 + hf * 8;
                float2 o = make_float2(acc[ma][na][hf * 2 + 0] + b0,
                                       acc[ma][na][hf * 2 + 1] + b1);
                *(float2*)(out + (size_t)m * CDIM + colg) = o;
            }
        }
    }
}

// ---------------------------------------------------------------------------
// fp32 -> fp16 hi/lo split for x
// ---------------------------------------------------------------------------
__global__ void split_x_kernel(const float* __restrict__ in, int n) {
    int i = (blockIdx.x * blockDim.x + threadIdx.x) * 4;
    if (i >= n) return;
    float4 v = *(const float4*)(in + i);
    float vv[4] = {v.x, v.y, v.z, v.w};
    __half h[4], l[4];
#pragma unroll
    for (int j = 0; j < 4; j++) {
        h[j] = __float2half_rn(vv[j]);
        l[j] = __float2half_rn(vv[j] - __half2float(h[j]));
    }
    *(__half2*)(g_xhi + i)     = __halves2half2(h[0], h[1]);
    *(__half2*)(g_xhi + i + 2) = __halves2half2(h[2], h[3]);
    *(__half2*)(g_xlo + i)     = __halves2half2(l[0], l[1]);
    *(__half2*)(g_xlo + i + 2) = __halves2half2(l[2], l[3]);
}

// fp32 -> fp16 convert for weights. which: 0 = w_qkv, 1 = w_proj
__global__ void conv_w_kernel(const float* __restrict__ in, int which, int n) {
    __half* dst = (which == 0) ? g_wqkv : g_wproj;
    int i = (blockIdx.x * blockDim.x + threadIdx.x) * 4;
    if (i >= n) return;
    float4 v = *(const float4*)(in + i);
    *(__half2*)(dst + i)     = __halves2half2(__float2half_rn(v.x), __float2half_rn(v.y));
    *(__half2*)(dst + i + 2) = __halves2half2(__float2half_rn(v.z), __float2half_rn(v.w));
}

// ---------------------------------------------------------------------------
// kv partials: per (bh, split of 256 tokens): kv[d][e], ksum[d]
// ---------------------------------------------------------------------------
__global__ __launch_bounds__(256) void kv_part_kernel() {
    __shared__ __align__(16) float ks[32][64];
    __shared__ __align__(16) float vs[32][64];
    const int tid = threadIdx.x;
    const int bh = blockIdx.x >> 4;
    const int sp = blockIdx.x & 15;
    const float* kp = g_k + (size_t)bh * NTOK * HD;
    const float* vp = g_v + (size_t)bh * NTOK * HD;
    const int lrow = tid >> 3;
    const int lcol = (tid & 7) * 8;
    const int tx = tid & 15, ty = tid >> 4;
    const int e0 = tx * 4, d0 = ty * 4;

    float acc[4][4];
#pragma unroll
    for (int i = 0; i < 4; i++)
#pragma unroll
        for (int j = 0; j < 4; j++) acc[i][j] = 0.f;
    float ksacc = 0.f;

    const int nbeg = sp * (NTOK / KVSPLIT);
    for (int n0 = nbeg; n0 < nbeg + (NTOK / KVSPLIT); n0 += 32) {
        __syncthreads();
        const float* kr = kp + (size_t)(n0 + lrow) * HD + lcol;
        const float* vr = vp + (size_t)(n0 + lrow) * HD + lcol;
        *(float4*)&ks[lrow][lcol]     = *(const float4*)kr;
        *(float4*)&ks[lrow][lcol + 4] = *(const float4*)(kr + 4);
        *(float4*)&vs[lrow][lcol]     = *(const float4*)vr;
        *(float4*)&vs[lrow][lcol + 4] = *(const float4*)(vr + 4);
        __syncthreads();
#pragma unroll 4
        for (int nn = 0; nn < 32; nn++) {
            float kf[4], vf[4];
            *(float4*)kf = *(const float4*)&ks[nn][d0];
            *(float4*)vf = *(const float4*)&vs[nn][e0];
#pragma unroll
            for (int i = 0; i < 4; i++)
#pragma unroll
                for (int j = 0; j < 4; j++) acc[i][j] += kf[i] * vf[j];
        }
        if (tid < 64) {
#pragma unroll 4
            for (int nn = 0; nn < 32; nn++) ksacc += ks[nn][tid];
        }
    }

    float* kvout = g_kv_part + (size_t)(sp * NBH + bh) * (HD * HD);
#pragma unroll
    for (int i = 0; i < 4; i++)
        *(float4*)(kvout + (d0 + i) * HD + e0) =
            make_float4(acc[i][0], acc[i][1], acc[i][2], acc[i][3]);
    if (tid < 64) g_ksum_part[(sp * NBH + bh) * HD + tid] = ksacc;
}

__global__ void kv_reduce_kernel() {
    const int bh = blockIdx.x;
    const int tid = threadIdx.x;
    for (int j = tid; j < HD * HD; j += 256) {
        float s = 0.f;
#pragma unroll
        for (int p = 0; p < KVSPLIT; p++)
            s += g_kv_part[(size_t)(p * NBH + bh) * (HD * HD) + j];
        g_kv[(size_t)bh * HD * HD + j] = s;
    }
    if (tid < HD) {
        float s = 0.f;
#pragma unroll
        for (int p = 0; p < KVSPLIT; p++)
            s += g_ksum_part[(p * NBH + bh) * HD + tid];
        g_ksum[bh * HD + tid] = s;
    }
}

// ---------------------------------------------------------------------------
// attn numerator + normalize; writes fp16 hi/lo for the proj GEMM.
// ---------------------------------------------------------------------------
#define QT_STRIDE 129
#define SMEM_NUM_BYTES ((64 * QT_STRIDE + 64 * 64 + 64) * 4)

__global__ __launch_bounds__(128) void attn_num_kernel() {
    extern __shared__ float sm[];
    float* qt  = sm;
    float* kvs = sm + 64 * QT_STRIDE;
    float* kss = kvs + 64 * 64;
    const int tid = threadIdx.x;
    const int bh = blockIdx.y;
    const int b = bh >> 4, h = bh & 15;
    const int row0 = blockIdx.x * 128;
    const float* qp  = g_q + ((size_t)bh * NTOK + row0) * HD;
    const float* kvp = g_kv + (size_t)bh * HD * HD;

#pragma unroll
    for (int c = 0; c < 8; c++) {
        int g = (c * 128 + tid) * 4;
        *(float4*)&kvs[g] = *(const float4*)(kvp + g);
    }
    if (tid < 64) kss[tid] = g_ksum[bh * HD + tid];
#pragma unroll
    for (int c = 0; c < 16; c++) {
        int f = c * 128 + tid;
        float4 qv = *(const float4*)(qp + f * 4);
        int row = f >> 4;
        int col = (f & 15) * 4;
        qt[(col + 0) * QT_STRIDE + row] = qv.x;
        qt[(col + 1) * QT_STRIDE + row] = qv.y;
        qt[(col + 2) * QT_STRIDE + row] = qv.z;
        qt[(col + 3) * QT_STRIDE + row] = qv.w;
    }
    __syncthreads();

    float acc[64];
#pragma unroll
    for (int e = 0; e < 64; e++) acc[e] = 0.f;
    float qk = 0.f;
#pragma unroll 4
    for (int d = 0; d < 64; d++) {
        float qd = qt[d * QT_STRIDE + tid];
        qk += qd * kss[d];
        const float4* kr = (const float4*)&kvs[d * 64];
#pragma unroll
        for (int e4 = 0; e4 < 16; e4++) {
            float4 kv4 = kr[e4];
            acc[e4 * 4 + 0] += qd * kv4.x;
            acc[e4 * 4 + 1] += qd * kv4.y;
            acc[e4 * 4 + 2] += qd * kv4.z;
            acc[e4 * 4 + 3] += qd * kv4.w;
        }
    }

    const float inv = 1.f / (qk + 1e-8f);
    const size_t obase = ((size_t)(b * NTOK + row0 + tid)) * CDIM + h * HD;
    __half* ph = g_attn_hi + obase;
    __half* pl = g_attn_lo + obase;
#pragma unroll
    for (int e2 = 0; e2 < 32; e2++) {
        float o0 = acc[2 * e2 + 0] * inv;
        float o1 = acc[2 * e2 + 1] * inv;
        __half h0 = __float2half_rn(o0);
        __half h1 = __float2half_rn(o1);
        __half l0 = __float2half_rn(o0 - __half2float(h0));
        __half l1 = __float2half_rn(o1 - __half2float(h1));
        *(__half2*)(ph + 2 * e2) = __halves2half2(h0, h1);
        *(__half2*)(pl + 2 * e2) = __halves2half2(l0, l1);
    }
}

// ---------------------------------------------------------------------------
extern "C" void kernel_launch(void* const* d_in, const int* in_sizes, int n_in,
                              void* d_out, int out_size) {
    const float* x      = (const float*)d_in[0];
    const float* w_qkv  = (const float*)d_in[1];
    const float* w_proj = (const float*)d_in[2];
    const float* b_proj = (const float*)d_in[3];
    float* out = (float*)d_out;

    cudaFuncSetAttribute(gemm_qkv_mma, cudaFuncAttributeMaxDynamicSharedMemorySize,
                         SMEM_GEMM_BYTES);
    cudaFuncSetAttribute(gemm_proj_mma, cudaFuncAttributeMaxDynamicSharedMemorySize,
                         SMEM_GEMM_BYTES);
    cudaFuncSetAttribute(attn_num_kernel, cudaFuncAttributeMaxDynamicSharedMemorySize,
                         SMEM_NUM_BYTES);

    split_x_kernel<<<(MTOT * KDIM) / 1024, 256>>>(x, MTOT * KDIM);
    conv_w_kernel<<<(NQKV * KDIM) / 1024, 256>>>(w_qkv, 0, NQKV * KDIM);
    conv_w_kernel<<<(CDIM * KDIM) / 1024, 256>>>(w_proj, 1, CDIM * KDIM);

    gemm_qkv_mma<<<dim3(NQKV / BN, MTOT / BM), 256, SMEM_GEMM_BYTES>>>();

    kv_part_kernel<<<NBH * KVSPLIT, 256>>>();
    kv_reduce_kernel<<<NBH, 256>>>();

    attn_num_kernel<<<dim3(NTOK / 128, NBH), 128, SMEM_NUM_BYTES>>>();

    gemm_proj_mma<<<dim3(CDIM / BN, MTOT / BM), 256, SMEM_GEMM_BYTES>>>(b_proj, out);
}

// round 7
// speedup vs baseline: 5.0816x; 1.2026x over previous
#include <cuda_runtime.h>
#include <cuda_fp16.h>
#include <math.h>
#include <stdint.h>

#define NB    4
#define NTOK  4096
#define CDIM  1024
#define NH    16
#define HD    64
#define NBH   64
#define MTOT  16384
#define KDIM  1024
#define NQKV  3072

// GEMM tiling
#define BM 128
#define BN 128
#define BK 64
#define NCHUNK (KDIM / BK)      // 16
#define TILE_BYTES (128 * 128)              // 16384
#define OFF_AHI 0
#define OFF_ALO (1 * TILE_BYTES)
#define OFF_B   (2 * TILE_BYTES)
#define STAGE_BYTES (3 * TILE_BYTES)        // 49152
#define SMEM_GEMM_BYTES (2 * STAGE_BYTES)   // 98304

// SW128 swizzle
#define SWZ(o) ((o) ^ (((o) >> 3) & 0x70))

#define KVSPLIT 16
#define KV_STAGE 24576
#define SMEM_KV_BYTES (2 * KV_STAGE + 1024)   // 50176

// attn kernel smem offsets
#define AT_QHI  0
#define AT_QLO  16384
#define AT_KVHI 32768
#define AT_KVLO 40960
#define AT_KSUM 49152
#define AT_INV  49408
#define SMEM_AT_BYTES 49920

// ---------------------------------------------------------------------------
// Scratch (device globals)
// ---------------------------------------------------------------------------
__device__ __half g_xhi[MTOT * KDIM];
__device__ __half g_xlo[MTOT * KDIM];
__device__ __half g_wqkv[NQKV * KDIM];
__device__ __half g_wproj[CDIM * KDIM];
__device__ __half g_qhi[NBH * NTOK * HD];
__device__ __half g_qlo[NBH * NTOK * HD];
__device__ __half g_khi[NBH * NTOK * HD];
__device__ __half g_klo[NBH * NTOK * HD];
__device__ __half g_v[NBH * NTOK * HD];
__device__ float g_kv_part[KVSPLIT * NBH * HD * HD];
__device__ float g_ksum_part[KVSPLIT * NBH * HD];
__device__ float g_ksum[NBH * HD];
__device__ __half g_kvT_hi[NBH * HD * HD];
__device__ __half g_kvT_lo[NBH * HD * HD];
__device__ __half g_attn_hi[MTOT * CDIM];
__device__ __half g_attn_lo[MTOT * CDIM];

__device__ __forceinline__ float elu1(float x) {
    return x > 0.f ? x + 1.f : expf(x);
}

// ---------------------------------------------------------------------------
// PTX helpers (compute_103-safe)
// ---------------------------------------------------------------------------
__device__ __forceinline__ uint32_t smem_u32(const void* p) {
    uint32_t a;
    asm("{ .reg .u64 t; cvta.to.shared.u64 t, %1; cvt.u32.u64 %0, t; }" : "=r"(a) : "l"(p));
    return a;
}
__device__ __forceinline__ void cp16(uint32_t s, const void* g) {
    asm volatile("cp.async.cg.shared.global [%0], [%1], 16;" :: "r"(s), "l"(g));
}
#define CP_COMMIT() asm volatile("cp.async.commit_group;" ::: "memory")
#define CP_WAIT0()  asm volatile("cp.async.wait_group 0;" ::: "memory")

__device__ __forceinline__ void ldm4(uint32_t* r, uint32_t addr) {
    asm volatile("ldmatrix.sync.aligned.m8n8.x4.shared.b16 {%0,%1,%2,%3}, [%4];"
                 : "=r"(r[0]), "=r"(r[1]), "=r"(r[2]), "=r"(r[3]) : "r"(addr));
}
__device__ __forceinline__ void ldm4t(uint32_t* r, uint32_t addr) {
    asm volatile("ldmatrix.sync.aligned.m8n8.x4.trans.shared.b16 {%0,%1,%2,%3}, [%4];"
                 : "=r"(r[0]), "=r"(r[1]), "=r"(r[2]), "=r"(r[3]) : "r"(addr));
}
__device__ __forceinline__ void mma16816(float* d, const uint32_t* a,
                                         uint32_t b0, uint32_t b1) {
    asm volatile(
        "mma.sync.aligned.m16n8k16.row.col.f32.f16.f16.f32 "
        "{%0,%1,%2,%3}, {%4,%5,%6,%7}, {%8,%9}, {%0,%1,%2,%3};"
        : "+f"(d[0]), "+f"(d[1]), "+f"(d[2]), "+f"(d[3])
        : "r"(a[0]), "r"(a[1]), "r"(a[2]), "r"(a[3]), "r"(b0), "r"(b1));
}

// ---------------------------------------------------------------------------
// GEMM stage loader (A-hi, A-lo, B): 128x64 fp16 tiles, SW128 rows
// ---------------------------------------------------------------------------
__device__ __forceinline__ void load_stage(
    uint32_t sbase,
    const __half* __restrict__ Ahi, const __half* __restrict__ Alo,
    const __half* __restrict__ B,
    int m0, int n0, int kc, int tid)
{
#pragma unroll
    for (int t = 0; t < 4; t++) {
        int idx = t * 256 + tid;
        int row = idx >> 3;
        int c16 = idx & 7;
        uint32_t so = SWZ((uint32_t)(row * 128 + c16 * 16));
        size_t ga = (size_t)(m0 + row) * KDIM + kc + c16 * 8;
        size_t gb = (size_t)(n0 + row) * KDIM + kc + c16 * 8;
        cp16(sbase + OFF_AHI + so, Ahi + ga);
        cp16(sbase + OFF_ALO + so, Alo + ga);
        cp16(sbase + OFF_B + so, B + gb);
    }
}

// ---------------------------------------------------------------------------
// GEMM mainloop: acc[2][8][4] += Ahi*B + Alo*B over K=1024. 2-stage, BK=64.
// ---------------------------------------------------------------------------
__device__ __forceinline__ void mma_mainloop(
    const __half* __restrict__ Ahi, const __half* __restrict__ Alo,
    const __half* __restrict__ B,
    int m0, int n0, uint32_t sm32, float acc[2][8][4])
{
    const int tid = threadIdx.x;
    const int lane = tid & 31;
    const int wid = tid >> 5;
    const int wm = wid & 3;
    const int wn = wid >> 2;

    load_stage(sm32, Ahi, Alo, B, m0, n0, 0, tid);
    CP_COMMIT();

    const int a_row = (lane & 15);
    const int a_koff = (lane & 16) ? 8 : 0;
    const int b_row = (lane & 7) + ((lane & 16) >> 1);
    const int b_koff = (lane & 8) ? 8 : 0;

    const uint32_t aoff0 = (uint32_t)((wm * 32 + a_row) * 128 + a_koff * 2);
    const uint32_t aoff1 = aoff0 + 16 * 128;
    uint32_t boffs[4];
#pragma unroll
    for (int nb = 0; nb < 4; nb++)
        boffs[nb] = (uint32_t)((wn * 64 + nb * 16 + b_row) * 128 + b_koff * 2);

    for (int c = 0; c < NCHUNK; c++) {
        CP_WAIT0();
        __syncthreads();

        if (c + 1 < NCHUNK) {
            load_stage(sm32 + ((c + 1) & 1) * STAGE_BYTES, Ahi, Alo, B,
                       m0, n0, (c + 1) * BK, tid);
            CP_COMMIT();
        }

        const uint32_t sb = sm32 + (c & 1) * STAGE_BYTES;
#pragma unroll
        for (int kk = 0; kk < BK; kk += 16) {
            uint32_t ah[2][4], al[2][4], bb[4][4];
            const uint32_t kb = (uint32_t)(kk * 2);
            ldm4(ah[0], sb + OFF_AHI + SWZ(aoff0 + kb));
            ldm4(ah[1], sb + OFF_AHI + SWZ(aoff1 + kb));
            ldm4(al[0], sb + OFF_ALO + SWZ(aoff0 + kb));
            ldm4(al[1], sb + OFF_ALO + SWZ(aoff1 + kb));
#pragma unroll
            for (int nb = 0; nb < 4; nb++)
                ldm4(bb[nb], sb + OFF_B + SWZ(boffs[nb] + kb));
#pragma unroll
            for (int ma = 0; ma < 2; ma++)
#pragma unroll
                for (int na = 0; na < 8; na++)
                    mma16816(acc[ma][na], ah[ma],
                             bb[na >> 1][(na & 1) * 2], bb[na >> 1][(na & 1) * 2 + 1]);
#pragma unroll
            for (int ma = 0; ma < 2; ma++)
#pragma unroll
                for (int na = 0; na < 8; na++)
                    mma16816(acc[ma][na], al[ma],
                             bb[na >> 1][(na & 1) * 2], bb[na >> 1][(na & 1) * 2 + 1]);
        }
    }
}

// ---------------------------------------------------------------------------
// QKV GEMM: epilogue applies elu+1 to q,k; writes q,k fp16 hi/lo, v fp16.
// ---------------------------------------------------------------------------
__global__ __launch_bounds__(256, 2) void gemm_qkv_mma() {
    extern __shared__ char smem[];
    const uint32_t sm32 = smem_u32(smem);
    const int m0 = blockIdx.y * BM;
    const int n0 = blockIdx.x * BN;

    float acc[2][8][4];
#pragma unroll
    for (int i = 0; i < 2; i++)
#pragma unroll
        for (int j = 0; j < 8; j++)
#pragma unroll
            for (int k = 0; k < 4; k++) acc[i][j][k] = 0.f;

    mma_mainloop(g_xhi, g_xlo, g_wqkv, m0, n0, sm32, acc);

    const int tid = threadIdx.x;
    const int lane = tid & 31;
    const int wid = tid >> 5;
    const int wm = wid & 3, wn = wid >> 2;
    const int r0 = lane >> 2;
    const int c0 = (lane & 3) * 2;

#pragma unroll
    for (int ma = 0; ma < 2; ma++) {
#pragma unroll
        for (int na = 0; na < 8; na++) {
            const int colg = n0 + wn * 64 + na * 8 + c0;
            const int part = colg >> 10;
            const int h = (colg & 1023) >> 6;
            const int d = colg & 63;
#pragma unroll
            for (int hf = 0; hf < 2; hf++) {
                const int m = m0 + wm * 32 + ma * 16 + r0 + hf * 8;
                const int bb = m >> 12, t = m & 4095;
                float v0 = acc[ma][na][hf * 2 + 0];
                float v1 = acc[ma][na][hf * 2 + 1];
                size_t off = ((size_t)(bb * NH + h) * NTOK + t) * HD + d;
                if (part == 2) {
                    *(__half2*)(g_v + off) =
                        __halves2half2(__float2half_rn(v0), __float2half_rn(v1));
                } else {
                    v0 = elu1(v0); v1 = elu1(v1);
                    __half h0 = __float2half_rn(v0), h1 = __float2half_rn(v1);
                    __half l0 = __float2half_rn(v0 - __half2float(h0));
                    __half l1 = __float2half_rn(v1 - __half2float(h1));
                    __half2 hh = __halves2half2(h0, h1);
                    __half2 ll = __halves2half2(l0, l1);
                    if (part == 0) {
                        *(__half2*)(g_qhi + off) = hh;
                        *(__half2*)(g_qlo + off) = ll;
                    } else {
                        *(__half2*)(g_khi + off) = hh;
                        *(__half2*)(g_klo + off) = ll;
                    }
                }
            }
        }
    }
}

// ---------------------------------------------------------------------------
// Proj GEMM: out = attn @ w_proj^T + bias
// ---------------------------------------------------------------------------
__global__ __launch_bounds__(256, 2) void gemm_proj_mma(const float* __restrict__ bias,
                                                        float* __restrict__ out) {
    extern __shared__ char smem[];
    const uint32_t sm32 = smem_u32(smem);
    const int m0 = blockIdx.y * BM;
    const int n0 = blockIdx.x * BN;

    float acc[2][8][4];
#pragma unroll
    for (int i = 0; i < 2; i++)
#pragma unroll
        for (int j = 0; j < 8; j++)
#pragma unroll
            for (int k = 0; k < 4; k++) acc[i][j][k] = 0.f;

    mma_mainloop(g_attn_hi, g_attn_lo, g_wproj, m0, n0, sm32, acc);

    const int tid = threadIdx.x;
    const int lane = tid & 31;
    const int wid = tid >> 5;
    const int wm = wid & 3, wn = wid >> 2;
    const int r0 = lane >> 2;
    const int c0 = (lane & 3) * 2;

#pragma unroll
    for (int ma = 0; ma < 2; ma++) {
#pragma unroll
        for (int na = 0; na < 8; na++) {
            const int colg = n0 + wn * 64 + na * 8 + c0;
            const float b0 = bias[colg], b1 = bias[colg + 1];
#pragma unroll
            for (int hf = 0; hf < 2; hf++) {
                const int m = m0 + wm * 32 + ma * 16 + r0 + hf * 8;
                float2 o = make_float2(acc[ma][na][hf * 2 + 0] + b0,
                                       acc[ma][na][hf * 2 + 1] + b1);
                *(float2*)(out + (size_t)m * CDIM + colg) = o;
            }
        }
    }
}

// ---------------------------------------------------------------------------
// fp32 -> fp16 hi/lo split for x; fp16 convert for weights
// ---------------------------------------------------------------------------
__global__ void split_x_kernel(const float* __restrict__ in, int n) {
    int i = (blockIdx.x * blockDim.x + threadIdx.x) * 4;
    if (i >= n) return;
    float4 v = *(const float4*)(in + i);
    float vv[4] = {v.x, v.y, v.z, v.w};
    __half h[4], l[4];
#pragma unroll
    for (int j = 0; j < 4; j++) {
        h[j] = __float2half_rn(vv[j]);
        l[j] = __float2half_rn(vv[j] - __half2float(h[j]));
    }
    *(__half2*)(g_xhi + i)     = __halves2half2(h[0], h[1]);
    *(__half2*)(g_xhi + i + 2) = __halves2half2(h[2], h[3]);
    *(__half2*)(g_xlo + i)     = __halves2half2(l[0], l[1]);
    *(__half2*)(g_xlo + i + 2) = __halves2half2(l[2], l[3]);
}

__global__ void conv_w_kernel(const float* __restrict__ in, int which, int n) {
    __half* dst = (which == 0) ? g_wqkv : g_wproj;
    int i = (blockIdx.x * blockDim.x + threadIdx.x) * 4;
    if (i >= n) return;
    float4 v = *(const float4*)(in + i);
    *(__half2*)(dst + i)     = __halves2half2(__float2half_rn(v.x), __float2half_rn(v.y));
    *(__half2*)(dst + i + 2) = __halves2half2(__float2half_rn(v.z), __float2half_rn(v.w));
}

// ---------------------------------------------------------------------------
// kv via mma: per (bh, 1/16 split): kv[64d][64e] = khi^T v + klo^T v; ksum side.
// smem per stage: khi(8K) klo(8K) v(8K). 8 warps = 2(m) x 4(n).
// ---------------------------------------------------------------------------
__device__ __forceinline__ void kv_load_stage(uint32_t sb, size_t gbase, int tid) {
#pragma unroll
    for (int t = 0; t < 2; t++) {
        int u = t * 256 + tid;
        int row = u >> 3, cb = u & 7;
        uint32_t so = SWZ((uint32_t)(row * 128 + cb * 16));
        size_t g = gbase + (size_t)row * HD + cb * 8;
        cp16(sb + so, g_khi + g);
        cp16(sb + 8192 + so, g_klo + g);
        cp16(sb + 16384 + so, g_v + g);
    }
}

__global__ __launch_bounds__(256, 2) void kv_mma_kernel() {
    extern __shared__ char smem[];
    const uint32_t sm32 = smem_u32(smem);
    const int tid = threadIdx.x, lane = tid & 31, wid = tid >> 5;
    const int bh = blockIdx.x >> 4, sp = blockIdx.x & 15;
    const int wm = wid & 1, wn = wid >> 1;
    const size_t nbase = (size_t)bh * NTOK + sp * (NTOK / KVSPLIT);

    float acc[2][2][4];
#pragma unroll
    for (int i = 0; i < 2; i++)
#pragma unroll
        for (int j = 0; j < 2; j++)
#pragma unroll
            for (int k = 0; k < 4; k++) acc[i][j][k] = 0.f;
    float ksacc = 0.f;
    const int ks_d = tid & 63, ks_q = tid >> 6;

    kv_load_stage(sm32, nbase * HD, tid);
    CP_COMMIT();

    const int l7 = lane & 7, lg = lane >> 3;
    const int an_off = ((lg >> 1) ? 8 : 0) + l7;   // A: n row offset
    const int ad_off = (lg & 1) ? 8 : 0;           // A: d col offset
    const int bn_off = ((lg & 1) ? 8 : 0) + l7;    // B: n row offset
    const int be_off = (lg >> 1) ? 8 : 0;          // B: e col offset
    const int d0 = wm * 32;
    const int e0 = wn * 16;

    for (int c = 0; c < 4; c++) {
        CP_WAIT0();
        __syncthreads();
        if (c + 1 < 4) {
            kv_load_stage(sm32 + ((c + 1) & 1) * KV_STAGE,
                          (nbase + (c + 1) * 64) * HD, tid);
            CP_COMMIT();
        }
        const uint32_t sb = sm32 + (c & 1) * KV_STAGE;
#pragma unroll
        for (int kk = 0; kk < 64; kk += 16) {
            uint32_t ah[2][4], al[2][4], bv[4];
#pragma unroll
            for (int ma = 0; ma < 2; ma++) {
                uint32_t ad = SWZ((uint32_t)((kk + an_off) * 128 +
                                             (d0 + ma * 16 + ad_off) * 2));
                ldm4t(ah[ma], sb + ad);
                ldm4t(al[ma], sb + 8192 + ad);
            }
            uint32_t bd = SWZ((uint32_t)((kk + bn_off) * 128 + (e0 + be_off) * 2));
            ldm4t(bv, sb + 16384 + bd);
#pragma unroll
            for (int ma = 0; ma < 2; ma++)
#pragma unroll
                for (int nb = 0; nb < 2; nb++)
                    mma16816(acc[ma][nb], ah[ma], bv[nb * 2], bv[nb * 2 + 1]);
#pragma unroll
            for (int ma = 0; ma < 2; ma++)
#pragma unroll
                for (int nb = 0; nb < 2; nb++)
                    mma16816(acc[ma][nb], al[ma], bv[nb * 2], bv[nb * 2 + 1]);
        }
        // ksum side reduction over this chunk (khi + klo)
#pragma unroll
        for (int nn = 0; nn < 16; nn++) {
            int n = ks_q * 16 + nn;
            uint32_t off = SWZ((uint32_t)(n * 128 + ks_d * 2));
            float kh = __half2float(*(const __half*)(smem + (c & 1) * KV_STAGE + off));
            float kl = __half2float(*(const __half*)(smem + (c & 1) * KV_STAGE + 8192 + off));
            ksacc += kh + kl;
        }
    }

    float* kssm = (float*)(smem + 2 * KV_STAGE);
    kssm[ks_q * 64 + ks_d] = ksacc;
    __syncthreads();
    if (tid < 64) {
        float s = kssm[tid] + kssm[64 + tid] + kssm[128 + tid] + kssm[192 + tid];
        g_ksum_part[(sp * NBH + bh) * HD + tid] = s;
    }

    const int r0 = lane >> 2, c0 = (lane & 3) * 2;
    float* kvout = g_kv_part + (size_t)(sp * NBH + bh) * (HD * HD);
#pragma unroll
    for (int ma = 0; ma < 2; ma++)
#pragma unroll
        for (int nb = 0; nb < 2; nb++)
#pragma unroll
            for (int hf = 0; hf < 2; hf++) {
                int d = d0 + ma * 16 + r0 + hf * 8;
                int e = e0 + nb * 8 + c0;
                *(float2*)(kvout + d * 64 + e) =
                    make_float2(acc[ma][nb][hf * 2], acc[ma][nb][hf * 2 + 1]);
            }
}

// ---------------------------------------------------------------------------
// kv reduce: sum partials, write kvT fp16 hi/lo ([e][d]) + ksum fp32.
// ---------------------------------------------------------------------------
__global__ __launch_bounds__(256) void kv_reduce_kernel() {
    __shared__ float kvsm[64][65];
    const int bh = blockIdx.x;
    const int tid = threadIdx.x;
    for (int j = tid; j < HD * HD; j += 256) {
        float s = 0.f;
#pragma unroll
        for (int p = 0; p < KVSPLIT; p++)
            s += g_kv_part[(size_t)(p * NBH + bh) * (HD * HD) + j];
        kvsm[j >> 6][j & 63] = s;
    }
    if (tid < HD) {
        float s = 0.f;
#pragma unroll
        for (int p = 0; p < KVSPLIT; p++)
            s += g_ksum_part[(p * NBH + bh) * HD + tid];
        g_ksum[bh * HD + tid] = s;
    }
    __syncthreads();
    for (int j = tid; j < HD * HD; j += 256) {
        int e = j >> 6, d = j & 63;
        float v = kvsm[d][e];
        __half hi = __float2half_rn(v);
        __half lo = __float2half_rn(v - __half2float(hi));
        g_kvT_hi[(size_t)bh * (HD * HD) + j] = hi;
        g_kvT_lo[(size_t)bh * (HD * HD) + j] = lo;
    }
}

// ---------------------------------------------------------------------------
// attn via mma: num[128x64] = qhi@kvhi + qhi@kvlo + qlo@kvhi; /(q.ksum+eps);
// writes attn fp16 hi/lo. 8 warps = 4(m) x 2(n).
// ---------------------------------------------------------------------------
__global__ __launch_bounds__(256, 2) void attn_mma_kernel() {
    extern __shared__ char smem[];
    const uint32_t sm32 = smem_u32(smem);
    const int tid = threadIdx.x, lane = tid & 31, wid = tid >> 5;
    const int bh = blockIdx.y;
    const int bb = bh >> 4, h = bh & 15;
    const int row0 = blockIdx.x * 128;
    const int wm = wid & 3, wn = wid >> 2;

    // loads
    {
        size_t qbase = ((size_t)bh * NTOK + row0) * HD;
#pragma unroll
        for (int t = 0; t < 4; t++) {
            int u = t * 256 + tid;
            int row = u >> 3, cb = u & 7;
            uint32_t so = SWZ((uint32_t)(row * 128 + cb * 16));
            size_t g = qbase + (size_t)row * HD + cb * 8;
            cp16(sm32 + AT_QHI + so, g_qhi + g);
            cp16(sm32 + AT_QLO + so, g_qlo + g);
        }
#pragma unroll
        for (int t = 0; t < 2; t++) {
            int u = t * 256 + tid;
            int row = u >> 3, cb = u & 7;
            uint32_t so = SWZ((uint32_t)(row * 128 + cb * 16));
            size_t g = (size_t)bh * (HD * HD) + (size_t)row * HD + cb * 8;
            cp16(sm32 + AT_KVHI + so, g_kvT_hi + g);
            cp16(sm32 + AT_KVLO + so, g_kvT_lo + g);
        }
        if (tid < 64) ((float*)(smem + AT_KSUM))[tid] = g_ksum[bh * HD + tid];
        CP_COMMIT();
        CP_WAIT0();
        __syncthreads();
    }

    // qk denominator (fp32)
    {
        int row = tid >> 1, hh = tid & 1;
        float s = 0.f;
        const float* kss = (const float*)(smem + AT_KSUM);
#pragma unroll
        for (int dd = 0; dd < 32; dd++) {
            int d = hh * 32 + dd;
            uint32_t off = SWZ((uint32_t)(row * 128 + d * 2));
            float qv = __half2float(*(const __half*)(smem + AT_QHI + off)) +
                       __half2float(*(const __half*)(smem + AT_QLO + off));
            s += qv * kss[d];
        }
        s += __shfl_xor_sync(0xFFFFFFFFu, s, 1);
        if (hh == 0) ((float*)(smem + AT_INV))[row] = 1.f / (s + 1e-8f);
        __syncthreads();
    }

    float acc[2][4][4];
#pragma unroll
    for (int i = 0; i < 2; i++)
#pragma unroll
        for (int j = 0; j < 4; j++)
#pragma unroll
            for (int k = 0; k < 4; k++) acc[i][j][k] = 0.f;

    const int a_row = lane & 15;
    const int a_koff = (lane & 16) ? 8 : 0;
    const int b_row = (lane & 7) + ((lane & 16) >> 1);
    const int b_koff = (lane & 8) ? 8 : 0;

#pragma unroll
    for (int kk = 0; kk < 64; kk += 16) {
        uint32_t qh[2][4], ql[2][4], kvh[2][4], kvl[2][4];
#pragma unroll
        for (int ma = 0; ma < 2; ma++) {
            uint32_t ad = SWZ((uint32_t)((wm * 32 + ma * 16 + a_row) * 128 +
                                         (kk + a_koff) * 2));
            ldm4(qh[ma], sm32 + AT_QHI + ad);
            ldm4(ql[ma], sm32 + AT_QLO + ad);
        }
#pragma unroll
        for (int nb = 0; nb < 2; nb++) {
            uint32_t bd = SWZ((uint32_t)((wn * 32 + nb * 16 + b_row) * 128 +
                                         (kk + b_koff) * 2));
            ldm4(kvh[nb], sm32 + AT_KVHI + bd);
            ldm4(kvl[nb], sm32 + AT_KVLO + bd);
        }
#pragma unroll
        for (int ma = 0; ma < 2; ma++)
#pragma unroll
            for (int na = 0; na < 4; na++) {
                const int blk = na >> 1, pr = (na & 1) * 2;
                mma16816(acc[ma][na], qh[ma], kvh[blk][pr], kvh[blk][pr + 1]);
                mma16816(acc[ma][na], qh[ma], kvl[blk][pr], kvl[blk][pr + 1]);
                mma16816(acc[ma][na], ql[ma], kvh[blk][pr], kvh[blk][pr + 1]);
            }
    }

    const int r0 = lane >> 2, c0 = (lane & 3) * 2;
    const float* invp = (const float*)(smem + AT_INV);
#pragma unroll
    for (int ma = 0; ma < 2; ma++)
#pragma unroll
        for (int na = 0; na < 4; na++)
#pragma unroll
            for (int hf = 0; hf < 2; hf++) {
                int row = wm * 32 + ma * 16 + r0 + hf * 8;
                float iv = invp[row];
                int e = wn * 32 + na * 8 + c0;
                float v0 = acc[ma][na][hf * 2 + 0] * iv;
                float v1 = acc[ma][na][hf * 2 + 1] * iv;
                __half h0 = __float2half_rn(v0), h1 = __float2half_rn(v1);
                __half l0 = __float2half_rn(v0 - __half2float(h0));
                __half l1 = __float2half_rn(v1 - __half2float(h1));
                size_t ob = ((size_t)(bb * NTOK + row0 + row)) * CDIM + h * HD + e;
                *(__half2*)(g_attn_hi + ob) = __halves2half2(h0, h1);
                *(__half2*)(g_attn_lo + ob) = __halves2half2(l0, l1);
            }
}

// ---------------------------------------------------------------------------
extern "C" void kernel_launch(void* const* d_in, const int* in_sizes, int n_in,
                              void* d_out, int out_size) {
    const float* x      = (const float*)d_in[0];
    const float* w_qkv  = (const float*)d_in[1];
    const float* w_proj = (const float*)d_in[2];
    const float* b_proj = (const float*)d_in[3];
    float* out = (float*)d_out;

    cudaFuncSetAttribute(gemm_qkv_mma, cudaFuncAttributeMaxDynamicSharedMemorySize,
                         SMEM_GEMM_BYTES);
    cudaFuncSetAttribute(gemm_proj_mma, cudaFuncAttributeMaxDynamicSharedMemorySize,
                         SMEM_GEMM_BYTES);
    cudaFuncSetAttribute(kv_mma_kernel, cudaFuncAttributeMaxDynamicSharedMemorySize,
                         SMEM_KV_BYTES);
    cudaFuncSetAttribute(attn_mma_kernel, cudaFuncAttributeMaxDynamicSharedMemorySize,
                         SMEM_AT_BYTES);

    split_x_kernel<<<(MTOT * KDIM) / 1024, 256>>>(x, MTOT * KDIM);
    conv_w_kernel<<<(NQKV * KDIM) / 1024, 256>>>(w_qkv, 0, NQKV * KDIM);
    conv_w_kernel<<<(CDIM * KDIM) / 1024, 256>>>(w_proj, 1, CDIM * KDIM);

    gemm_qkv_mma<<<dim3(NQKV / BN, MTOT / BM), 256, SMEM_GEMM_BYTES>>>();

    kv_mma_kernel<<<NBH * KVSPLIT, 256, SMEM_KV_BYTES>>>();
    kv_reduce_kernel<<<NBH, 256>>>();

    attn_mma_kernel<<<dim3(NTOK / 128, NBH), 256, SMEM_AT_BYTES>>>();

    gemm_proj_mma<<<dim3(CDIM / BN, MTOT / BM), 256, SMEM_GEMM_BYTES>>>(b_proj, out);
}

// round 8
// speedup vs baseline: 8.1305x; 1.6000x over previous
#include <cuda_runtime.h>
#include <cuda_fp16.h>
#include <math.h>
#include <stdint.h>

#define NB    4
#define NTOK  4096
#define CDIM  1024
#define NH    16
#define HD    64
#define NBH   64
#define MTOT  16384
#define KDIM  1024
#define NQKV  3072

// GEMM tiling: single-pass fp16, 3-stage pipeline
#define BM 128
#define BN 128
#define BK 64
#define NCHUNK (KDIM / BK)      // 16
#define TILE_BYTES (128 * 128)              // 16384
#define OFF_A 0
#define OFF_B TILE_BYTES
#define STAGE_BYTES (2 * TILE_BYTES)        // 32768
#define NSTAGE 3
#define SMEM_GEMM_BYTES (NSTAGE * STAGE_BYTES)  // 98304

// SW128 swizzle
#define SWZ(o) ((o) ^ (((o) >> 3) & 0x70))

#define KVSPLIT 16
#define KV_STAGE 24576
#define SMEM_KV_BYTES (2 * KV_STAGE + 1024)   // 50176

// attn kernel smem offsets
#define AT_QHI  0
#define AT_QLO  16384
#define AT_KVHI 32768
#define AT_KVLO 40960
#define AT_KSUM 49152
#define AT_INV  49408
#define SMEM_AT_BYTES 49920

// ---------------------------------------------------------------------------
// Scratch (device globals)
// ---------------------------------------------------------------------------
__device__ __half g_x16[MTOT * KDIM];
__device__ __half g_wqkv[NQKV * KDIM];
__device__ __half g_wproj[CDIM * KDIM];
__device__ __half g_qhi[NBH * NTOK * HD];
__device__ __half g_qlo[NBH * NTOK * HD];
__device__ __half g_khi[NBH * NTOK * HD];
__device__ __half g_klo[NBH * NTOK * HD];
__device__ __half g_v[NBH * NTOK * HD];
__device__ float g_kv_part[KVSPLIT * NBH * HD * HD];
__device__ float g_ksum_part[KVSPLIT * NBH * HD];
__device__ float g_ksum[NBH * HD];
__device__ __half g_kvT_hi[NBH * HD * HD];
__device__ __half g_kvT_lo[NBH * HD * HD];
__device__ __half g_attn[MTOT * CDIM];

__device__ __forceinline__ float elu1(float x) {
    return x > 0.f ? x + 1.f : expf(x);
}

// ---------------------------------------------------------------------------
// PTX helpers (compute_103-safe)
// ---------------------------------------------------------------------------
__device__ __forceinline__ uint32_t smem_u32(const void* p) {
    uint32_t a;
    asm("{ .reg .u64 t; cvta.to.shared.u64 t, %1; cvt.u32.u64 %0, t; }" : "=r"(a) : "l"(p));
    return a;
}
__device__ __forceinline__ void cp16(uint32_t s, const void* g) {
    asm volatile("cp.async.cg.shared.global [%0], [%1], 16;" :: "r"(s), "l"(g));
}
#define CP_COMMIT() asm volatile("cp.async.commit_group;" ::: "memory")
#define CP_WAIT1()  asm volatile("cp.async.wait_group 1;" ::: "memory")
#define CP_WAIT0()  asm volatile("cp.async.wait_group 0;" ::: "memory")

__device__ __forceinline__ void ldm4(uint32_t* r, uint32_t addr) {
    asm volatile("ldmatrix.sync.aligned.m8n8.x4.shared.b16 {%0,%1,%2,%3}, [%4];"
                 : "=r"(r[0]), "=r"(r[1]), "=r"(r[2]), "=r"(r[3]) : "r"(addr));
}
__device__ __forceinline__ void ldm4t(uint32_t* r, uint32_t addr) {
    asm volatile("ldmatrix.sync.aligned.m8n8.x4.trans.shared.b16 {%0,%1,%2,%3}, [%4];"
                 : "=r"(r[0]), "=r"(r[1]), "=r"(r[2]), "=r"(r[3]) : "r"(addr));
}
__device__ __forceinline__ void mma16816(float* d, const uint32_t* a,
                                         uint32_t b0, uint32_t b1) {
    asm volatile(
        "mma.sync.aligned.m16n8k16.row.col.f32.f16.f16.f32 "
        "{%0,%1,%2,%3}, {%4,%5,%6,%7}, {%8,%9}, {%0,%1,%2,%3};"
        : "+f"(d[0]), "+f"(d[1]), "+f"(d[2]), "+f"(d[3])
        : "r"(a[0]), "r"(a[1]), "r"(a[2]), "r"(a[3]), "r"(b0), "r"(b1));
}

// ---------------------------------------------------------------------------
// GEMM stage loader (A, B): 128x64 fp16 tiles, SW128 rows. 8 cp16/thread.
// ---------------------------------------------------------------------------
__device__ __forceinline__ void load_stage(
    uint32_t sbase,
    const __half* __restrict__ A, const __half* __restrict__ B,
    int m0, int n0, int kc, int tid)
{
#pragma unroll
    for (int t = 0; t < 4; t++) {
        int idx = t * 256 + tid;
        int row = idx >> 3;
        int c16 = idx & 7;
        uint32_t so = SWZ((uint32_t)(row * 128 + c16 * 16));
        cp16(sbase + OFF_A + so, A + (size_t)(m0 + row) * KDIM + kc + c16 * 8);
        cp16(sbase + OFF_B + so, B + (size_t)(n0 + row) * KDIM + kc + c16 * 8);
    }
}

// ---------------------------------------------------------------------------
// GEMM mainloop: acc[2][8][4] += A*B over K=1024. Single pass, 3-stage.
// ---------------------------------------------------------------------------
__device__ __forceinline__ void mma_mainloop(
    const __half* __restrict__ A, const __half* __restrict__ B,
    int m0, int n0, uint32_t sm32, float acc[2][8][4])
{
    const int tid = threadIdx.x;
    const int lane = tid & 31;
    const int wid = tid >> 5;
    const int wm = wid & 3;
    const int wn = wid >> 2;

    load_stage(sm32, A, B, m0, n0, 0, tid);
    CP_COMMIT();
    load_stage(sm32 + STAGE_BYTES, A, B, m0, n0, BK, tid);
    CP_COMMIT();

    const int a_row = (lane & 15);
    const int a_koff = (lane & 16) ? 8 : 0;
    const int b_row = (lane & 7) + ((lane & 16) >> 1);
    const int b_koff = (lane & 8) ? 8 : 0;

    const uint32_t aoff0 = (uint32_t)((wm * 32 + a_row) * 128 + a_koff * 2);
    const uint32_t aoff1 = aoff0 + 16 * 128;
    uint32_t boffs[4];
#pragma unroll
    for (int nb = 0; nb < 4; nb++)
        boffs[nb] = (uint32_t)((wn * 64 + nb * 16 + b_row) * 128 + b_koff * 2);

    int cur = 0, pre = 2;
    for (int c = 0; c < NCHUNK; c++) {
        if (c == NCHUNK - 1) CP_WAIT0(); else CP_WAIT1();
        __syncthreads();

        if (c + 2 < NCHUNK) {
            load_stage(sm32 + pre * STAGE_BYTES, A, B, m0, n0, (c + 2) * BK, tid);
            CP_COMMIT();
        }

        const uint32_t sb = sm32 + cur * STAGE_BYTES;
#pragma unroll
        for (int kk = 0; kk < BK; kk += 16) {
            uint32_t aa[2][4], bb[4][4];
            const uint32_t kb = (uint32_t)(kk * 2);
            ldm4(aa[0], sb + OFF_A + SWZ(aoff0 + kb));
            ldm4(aa[1], sb + OFF_A + SWZ(aoff1 + kb));
#pragma unroll
            for (int nb = 0; nb < 4; nb++)
                ldm4(bb[nb], sb + OFF_B + SWZ(boffs[nb] + kb));
#pragma unroll
            for (int ma = 0; ma < 2; ma++)
#pragma unroll
                for (int na = 0; na < 8; na++)
                    mma16816(acc[ma][na], aa[ma],
                             bb[na >> 1][(na & 1) * 2], bb[na >> 1][(na & 1) * 2 + 1]);
        }
        cur = (cur == NSTAGE - 1) ? 0 : cur + 1;
        pre = (pre == NSTAGE - 1) ? 0 : pre + 1;
    }
}

// ---------------------------------------------------------------------------
// QKV GEMM: epilogue applies elu+1 to q,k; writes q,k fp16 hi/lo, v fp16.
// ---------------------------------------------------------------------------
__global__ __launch_bounds__(256, 2) void gemm_qkv_mma() {
    extern __shared__ char smem[];
    const uint32_t sm32 = smem_u32(smem);
    const int m0 = blockIdx.y * BM;
    const int n0 = blockIdx.x * BN;

    float acc[2][8][4];
#pragma unroll
    for (int i = 0; i < 2; i++)
#pragma unroll
        for (int j = 0; j < 8; j++)
#pragma unroll
            for (int k = 0; k < 4; k++) acc[i][j][k] = 0.f;

    mma_mainloop(g_x16, g_wqkv, m0, n0, sm32, acc);

    const int tid = threadIdx.x;
    const int lane = tid & 31;
    const int wid = tid >> 5;
    const int wm = wid & 3, wn = wid >> 2;
    const int r0 = lane >> 2;
    const int c0 = (lane & 3) * 2;

#pragma unroll
    for (int ma = 0; ma < 2; ma++) {
#pragma unroll
        for (int na = 0; na < 8; na++) {
            const int colg = n0 + wn * 64 + na * 8 + c0;
            const int part = colg >> 10;
            const int h = (colg & 1023) >> 6;
            const int d = colg & 63;
#pragma unroll
            for (int hf = 0; hf < 2; hf++) {
                const int m = m0 + wm * 32 + ma * 16 + r0 + hf * 8;
                const int bb = m >> 12, t = m & 4095;
                float v0 = acc[ma][na][hf * 2 + 0];
                float v1 = acc[ma][na][hf * 2 + 1];
                size_t off = ((size_t)(bb * NH + h) * NTOK + t) * HD + d;
                if (part == 2) {
                    *(__half2*)(g_v + off) =
                        __halves2half2(__float2half_rn(v0), __float2half_rn(v1));
                } else {
                    v0 = elu1(v0); v1 = elu1(v1);
                    __half h0 = __float2half_rn(v0), h1 = __float2half_rn(v1);
                    __half l0 = __float2half_rn(v0 - __half2float(h0));
                    __half l1 = __float2half_rn(v1 - __half2float(h1));
                    __half2 hh = __halves2half2(h0, h1);
                    __half2 ll = __halves2half2(l0, l1);
                    if (part == 0) {
                        *(__half2*)(g_qhi + off) = hh;
                        *(__half2*)(g_qlo + off) = ll;
                    } else {
                        *(__half2*)(g_khi + off) = hh;
                        *(__half2*)(g_klo + off) = ll;
                    }
                }
            }
        }
    }
}

// ---------------------------------------------------------------------------
// Proj GEMM: out = attn @ w_proj^T + bias
// ---------------------------------------------------------------------------
__global__ __launch_bounds__(256, 2) void gemm_proj_mma(const float* __restrict__ bias,
                                                        float* __restrict__ out) {
    extern __shared__ char smem[];
    const uint32_t sm32 = smem_u32(smem);
    const int m0 = blockIdx.y * BM;
    const int n0 = blockIdx.x * BN;

    float acc[2][8][4];
#pragma unroll
    for (int i = 0; i < 2; i++)
#pragma unroll
        for (int j = 0; j < 8; j++)
#pragma unroll
            for (int k = 0; k < 4; k++) acc[i][j][k] = 0.f;

    mma_mainloop(g_attn, g_wproj, m0, n0, sm32, acc);

    const int tid = threadIdx.x;
    const int lane = tid & 31;
    const int wid = tid >> 5;
    const int wm = wid & 3, wn = wid >> 2;
    const int r0 = lane >> 2;
    const int c0 = (lane & 3) * 2;

#pragma unroll
    for (int ma = 0; ma < 2; ma++) {
#pragma unroll
        for (int na = 0; na < 8; na++) {
            const int colg = n0 + wn * 64 + na * 8 + c0;
            const float b0 = bias[colg], b1 = bias[colg + 1];
#pragma unroll
            for (int hf = 0; hf < 2; hf++) {
                const int m = m0 + wm * 32 + ma * 16 + r0 + hf * 8;
                float2 o = make_float2(acc[ma][na][hf * 2 + 0] + b0,
                                       acc[ma][na][hf * 2 + 1] + b1);
                *(float2*)(out + (size_t)m * CDIM + colg) = o;
            }
        }
    }
}

// ---------------------------------------------------------------------------
// fp32 -> fp16 converts. which: 0 = x, 1 = w_qkv, 2 = w_proj
// ---------------------------------------------------------------------------
__global__ void conv16_kernel(const float* __restrict__ in, int which, int n) {
    __half* dst = (which == 0) ? g_x16 : (which == 1) ? g_wqkv : g_wproj;
    int i = (blockIdx.x * blockDim.x + threadIdx.x) * 4;
    if (i >= n) return;
    float4 v = *(const float4*)(in + i);
    *(__half2*)(dst + i)     = __halves2half2(__float2half_rn(v.x), __float2half_rn(v.y));
    *(__half2*)(dst + i + 2) = __halves2half2(__float2half_rn(v.z), __float2half_rn(v.w));
}

// ---------------------------------------------------------------------------
// kv via mma: per (bh, 1/16 split): kv[64d][64e] = khi^T v + klo^T v; ksum side.
// ---------------------------------------------------------------------------
__device__ __forceinline__ void kv_load_stage(uint32_t sb, size_t gbase, int tid) {
#pragma unroll
    for (int t = 0; t < 2; t++) {
        int u = t * 256 + tid;
        int row = u >> 3, cb = u & 7;
        uint32_t so = SWZ((uint32_t)(row * 128 + cb * 16));
        size_t g = gbase + (size_t)row * HD + cb * 8;
        cp16(sb + so, g_khi + g);
        cp16(sb + 8192 + so, g_klo + g);
        cp16(sb + 16384 + so, g_v + g);
    }
}

__global__ __launch_bounds__(256, 2) void kv_mma_kernel() {
    extern __shared__ char smem[];
    const uint32_t sm32 = smem_u32(smem);
    const int tid = threadIdx.x, lane = tid & 31, wid = tid >> 5;
    const int bh = blockIdx.x >> 4, sp = blockIdx.x & 15;
    const int wm = wid & 1, wn = wid >> 1;
    const size_t nbase = (size_t)bh * NTOK + sp * (NTOK / KVSPLIT);

    float acc[2][2][4];
#pragma unroll
    for (int i = 0; i < 2; i++)
#pragma unroll
        for (int j = 0; j < 2; j++)
#pragma unroll
            for (int k = 0; k < 4; k++) acc[i][j][k] = 0.f;
    float ksacc = 0.f;
    const int ks_d = tid & 63, ks_q = tid >> 6;

    kv_load_stage(sm32, nbase * HD, tid);
    CP_COMMIT();

    const int l7 = lane & 7, lg = lane >> 3;
    const int an_off = ((lg >> 1) ? 8 : 0) + l7;
    const int ad_off = (lg & 1) ? 8 : 0;
    const int bn_off = ((lg & 1) ? 8 : 0) + l7;
    const int be_off = (lg >> 1) ? 8 : 0;
    const int d0 = wm * 32;
    const int e0 = wn * 16;

    for (int c = 0; c < 4; c++) {
        CP_WAIT0();
        __syncthreads();
        if (c + 1 < 4) {
            kv_load_stage(sm32 + ((c + 1) & 1) * KV_STAGE,
                          (nbase + (c + 1) * 64) * HD, tid);
            CP_COMMIT();
        }
        const uint32_t sb = sm32 + (c & 1) * KV_STAGE;
#pragma unroll
        for (int kk = 0; kk < 64; kk += 16) {
            uint32_t ah[2][4], al[2][4], bv[4];
#pragma unroll
            for (int ma = 0; ma < 2; ma++) {
                uint32_t ad = SWZ((uint32_t)((kk + an_off) * 128 +
                                             (d0 + ma * 16 + ad_off) * 2));
                ldm4t(ah[ma], sb + ad);
                ldm4t(al[ma], sb + 8192 + ad);
            }
            uint32_t bd = SWZ((uint32_t)((kk + bn_off) * 128 + (e0 + be_off) * 2));
            ldm4t(bv, sb + 16384 + bd);
#pragma unroll
            for (int ma = 0; ma < 2; ma++)
#pragma unroll
                for (int nb = 0; nb < 2; nb++)
                    mma16816(acc[ma][nb], ah[ma], bv[nb * 2], bv[nb * 2 + 1]);
#pragma unroll
            for (int ma = 0; ma < 2; ma++)
#pragma unroll
                for (int nb = 0; nb < 2; nb++)
                    mma16816(acc[ma][nb], al[ma], bv[nb * 2], bv[nb * 2 + 1]);
        }
#pragma unroll
        for (int nn = 0; nn < 16; nn++) {
            int n = ks_q * 16 + nn;
            uint32_t off = SWZ((uint32_t)(n * 128 + ks_d * 2));
            float kh = __half2float(*(const __half*)(smem + (c & 1) * KV_STAGE + off));
            float kl = __half2float(*(const __half*)(smem + (c & 1) * KV_STAGE + 8192 + off));
            ksacc += kh + kl;
        }
    }

    float* kssm = (float*)(smem + 2 * KV_STAGE);
    kssm[ks_q * 64 + ks_d] = ksacc;
    __syncthreads();
    if (tid < 64) {
        float s = kssm[tid] + kssm[64 + tid] + kssm[128 + tid] + kssm[192 + tid];
        g_ksum_part[(sp * NBH + bh) * HD + tid] = s;
    }

    const int r0 = lane >> 2, c0 = (lane & 3) * 2;
    float* kvout = g_kv_part + (size_t)(sp * NBH + bh) * (HD * HD);
#pragma unroll
    for (int ma = 0; ma < 2; ma++)
#pragma unroll
        for (int nb = 0; nb < 2; nb++)
#pragma unroll
            for (int hf = 0; hf < 2; hf++) {
                int d = d0 + ma * 16 + r0 + hf * 8;
                int e = e0 + nb * 8 + c0;
                *(float2*)(kvout + d * 64 + e) =
                    make_float2(acc[ma][nb][hf * 2], acc[ma][nb][hf * 2 + 1]);
            }
}

// ---------------------------------------------------------------------------
// kv reduce: sum partials, write kvT fp16 hi/lo ([e][d]) + ksum fp32.
// ---------------------------------------------------------------------------
__global__ __launch_bounds__(256) void kv_reduce_kernel() {
    __shared__ float kvsm[64][65];
    const int bh = blockIdx.x;
    const int tid = threadIdx.x;
    for (int j = tid; j < HD * HD; j += 256) {
        float s = 0.f;
#pragma unroll
        for (int p = 0; p < KVSPLIT; p++)
            s += g_kv_part[(size_t)(p * NBH + bh) * (HD * HD) + j];
        kvsm[j >> 6][j & 63] = s;
    }
    if (tid < HD) {
        float s = 0.f;
#pragma unroll
        for (int p = 0; p < KVSPLIT; p++)
            s += g_ksum_part[(p * NBH + bh) * HD + tid];
        g_ksum[bh * HD + tid] = s;
    }
    __syncthreads();
    for (int j = tid; j < HD * HD; j += 256) {
        int e = j >> 6, d = j & 63;
        float v = kvsm[d][e];
        __half hi = __float2half_rn(v);
        __half lo = __float2half_rn(v - __half2float(hi));
        g_kvT_hi[(size_t)bh * (HD * HD) + j] = hi;
        g_kvT_lo[(size_t)bh * (HD * HD) + j] = lo;
    }
}

// ---------------------------------------------------------------------------
// attn via mma: num = qhi@kvhi + qhi@kvlo + qlo@kvhi; /(q.ksum+eps);
// writes attn single fp16.
// ---------------------------------------------------------------------------
__global__ __launch_bounds__(256, 2) void attn_mma_kernel() {
    extern __shared__ char smem[];
    const uint32_t sm32 = smem_u32(smem);
    const int tid = threadIdx.x, lane = tid & 31, wid = tid >> 5;
    const int bh = blockIdx.y;
    const int bb = bh >> 4, h = bh & 15;
    const int row0 = blockIdx.x * 128;
    const int wm = wid & 3, wn = wid >> 2;

    {
        size_t qbase = ((size_t)bh * NTOK + row0) * HD;
#pragma unroll
        for (int t = 0; t < 4; t++) {
            int u = t * 256 + tid;
            int row = u >> 3, cb = u & 7;
            uint32_t so = SWZ((uint32_t)(row * 128 + cb * 16));
            size_t g = qbase + (size_t)row * HD + cb * 8;
            cp16(sm32 + AT_QHI + so, g_qhi + g);
            cp16(sm32 + AT_QLO + so, g_qlo + g);
        }
#pragma unroll
        for (int t = 0; t < 2; t++) {
            int u = t * 256 + tid;
            int row = u >> 3, cb = u & 7;
            uint32_t so = SWZ((uint32_t)(row * 128 + cb * 16));
            size_t g = (size_t)bh * (HD * HD) + (size_t)row * HD + cb * 8;
            cp16(sm32 + AT_KVHI + so, g_kvT_hi + g);
            cp16(sm32 + AT_KVLO + so, g_kvT_lo + g);
        }
        if (tid < 64) ((float*)(smem + AT_KSUM))[tid] = g_ksum[bh * HD + tid];
        CP_COMMIT();
        CP_WAIT0();
        __syncthreads();
    }

    {
        int row = tid >> 1, hh = tid & 1;
        float s = 0.f;
        const float* kss = (const float*)(smem + AT_KSUM);
#pragma unroll
        for (int dd = 0; dd < 32; dd++) {
            int d = hh * 32 + dd;
            uint32_t off = SWZ((uint32_t)(row * 128 + d * 2));
            float qv = __half2float(*(const __half*)(smem + AT_QHI + off)) +
                       __half2float(*(const __half*)(smem + AT_QLO + off));
            s += qv * kss[d];
        }
        s += __shfl_xor_sync(0xFFFFFFFFu, s, 1);
        if (hh == 0) ((float*)(smem + AT_INV))[row] = 1.f / (s + 1e-8f);
        __syncthreads();
    }

    float acc[2][4][4];
#pragma unroll
    for (int i = 0; i < 2; i++)
#pragma unroll
        for (int j = 0; j < 4; j++)
#pragma unroll
            for (int k = 0; k < 4; k++) acc[i][j][k] = 0.f;

    const int a_row = lane & 15;
    const int a_koff = (lane & 16) ? 8 : 0;
    const int b_row = (lane & 7) + ((lane & 16) >> 1);
    const int b_koff = (lane & 8) ? 8 : 0;

#pragma unroll
    for (int kk = 0; kk < 64; kk += 16) {
        uint32_t qh[2][4], ql[2][4], kvh[2][4], kvl[2][4];
#pragma unroll
        for (int ma = 0; ma < 2; ma++) {
            uint32_t ad = SWZ((uint32_t)((wm * 32 + ma * 16 + a_row) * 128 +
                                         (kk + a_koff) * 2));
            ldm4(qh[ma], sm32 + AT_QHI + ad);
            ldm4(ql[ma], sm32 + AT_QLO + ad);
        }
#pragma unroll
        for (int nb = 0; nb < 2; nb++) {
            uint32_t bd = SWZ((uint32_t)((wn * 32 + nb * 16 + b_row) * 128 +
                                         (kk + b_koff) * 2));
            ldm4(kvh[nb], sm32 + AT_KVHI + bd);
            ldm4(kvl[nb], sm32 + AT_KVLO + bd);
        }
#pragma unroll
        for (int ma = 0; ma < 2; ma++)
#pragma unroll
            for (int na = 0; na < 4; na++) {
                const int blk = na >> 1, pr = (na & 1) * 2;
                mma16816(acc[ma][na], qh[ma], kvh[blk][pr], kvh[blk][pr + 1]);
                mma16816(acc[ma][na], qh[ma], kvl[blk][pr], kvl[blk][pr + 1]);
                mma16816(acc[ma][na], ql[ma], kvh[blk][pr], kvh[blk][pr + 1]);
            }
    }

    const int r0 = lane >> 2, c0 = (lane & 3) * 2;
    const float* invp = (const float*)(smem + AT_INV);
#pragma unroll
    for (int ma = 0; ma < 2; ma++)
#pragma unroll
        for (int na = 0; na < 4; na++)
#pragma unroll
            for (int hf = 0; hf < 2; hf++) {
                int row = wm * 32 + ma * 16 + r0 + hf * 8;
                float iv = invp[row];
                int e = wn * 32 + na * 8 + c0;
                float v0 = acc[ma][na][hf * 2 + 0] * iv;
                float v1 = acc[ma][na][hf * 2 + 1] * iv;
                size_t ob = ((size_t)(bb * NTOK + row0 + row)) * CDIM + h * HD + e;
                *(__half2*)(g_attn + ob) =
                    __halves2half2(__float2half_rn(v0), __float2half_rn(v1));
            }
}

// ---------------------------------------------------------------------------
extern "C" void kernel_launch(void* const* d_in, const int* in_sizes, int n_in,
                              void* d_out, int out_size) {
    const float* x      = (const float*)d_in[0];
    const float* w_qkv  = (const float*)d_in[1];
    const float* w_proj = (const float*)d_in[2];
    const float* b_proj = (const float*)d_in[3];
    float* out = (float*)d_out;

    cudaFuncSetAttribute(gemm_qkv_mma, cudaFuncAttributeMaxDynamicSharedMemorySize,
                         SMEM_GEMM_BYTES);
    cudaFuncSetAttribute(gemm_proj_mma, cudaFuncAttributeMaxDynamicSharedMemorySize,
                         SMEM_GEMM_BYTES);
    cudaFuncSetAttribute(kv_mma_kernel, cudaFuncAttributeMaxDynamicSharedMemorySize,
                         SMEM_KV_BYTES);
    cudaFuncSetAttribute(attn_mma_kernel, cudaFuncAttributeMaxDynamicSharedMemorySize,
                         SMEM_AT_BYTES);

    conv16_kernel<<<(MTOT * KDIM) / 1024, 256>>>(x, 0, MTOT * KDIM);
    conv16_kernel<<<(NQKV * KDIM) / 1024, 256>>>(w_qkv, 1, NQKV * KDIM);
    conv16_kernel<<<(CDIM * KDIM) / 1024, 256>>>(w_proj, 2, CDIM * KDIM);

    gemm_qkv_mma<<<dim3(NQKV / BN, MTOT / BM), 256, SMEM_GEMM_BYTES>>>();

    kv_mma_kernel<<<NBH * KVSPLIT, 256, SMEM_KV_BYTES>>>();
    kv_reduce_kernel<<<NBH, 256>>>();

    attn_mma_kernel<<<dim3(NTOK / 128, NBH), 256, SMEM_AT_BYTES>>>();

    gemm_proj_mma<<<dim3(CDIM / BN, MTOT / BM), 256, SMEM_GEMM_BYTES>>>(b_proj, out);
}

// round 9
// speedup vs baseline: 8.9030x; 1.0950x over previous
#include <cuda_runtime.h>
#include <cuda_fp16.h>
#include <math.h>
#include <stdint.h>

#define NB    4
#define NTOK  4096
#define CDIM  1024
#define NH    16
#define HD    64
#define NBH   64
#define MTOT  16384
#define KDIM  1024
#define NQKV  3072

// GEMM tiling: single-pass fp16, 3-stage pipeline
#define BM 128
#define BN 128
#define BK 64
#define NCHUNK (KDIM / BK)      // 16
#define TILE_BYTES (128 * 128)              // 16384
#define OFF_A 0
#define OFF_B TILE_BYTES
#define STAGE_BYTES (2 * TILE_BYTES)        // 32768
#define NSTAGE 3
#define SMEM_GEMM_BYTES (NSTAGE * STAGE_BYTES)  // 98304

// SW128 swizzle
#define SWZ(o) ((o) ^ (((o) >> 3) & 0x70))

#define KVSPLIT 16
#define KV_STAGE 16384
#define SMEM_KV_BYTES (2 * KV_STAGE + 1024)   // 33792

// attn kernel smem offsets
#define AT_Q    0
#define AT_KV   16384
#define AT_KSUM 24576
#define AT_INV  24832
#define SMEM_AT_BYTES 25344

// ---------------------------------------------------------------------------
// Scratch (device globals)
// ---------------------------------------------------------------------------
__device__ __half g_x16[MTOT * KDIM];
__device__ __half g_wqkv[NQKV * KDIM];
__device__ __half g_wproj[CDIM * KDIM];
__device__ __half g_q16[NBH * NTOK * HD];
__device__ __half g_k16[NBH * NTOK * HD];
__device__ __half g_v[NBH * NTOK * HD];
__device__ float g_kv_part[KVSPLIT * NBH * HD * HD];
__device__ float g_ksum_part[KVSPLIT * NBH * HD];
__device__ float g_ksum[NBH * HD];
__device__ __half g_kvT[NBH * HD * HD];
__device__ __half g_attn[MTOT * CDIM];

__device__ __forceinline__ float elu1(float x) {
    return x > 0.f ? x + 1.f : expf(x);
}

// ---------------------------------------------------------------------------
// PTX helpers (compute_103-safe)
// ---------------------------------------------------------------------------
__device__ __forceinline__ uint32_t smem_u32(const void* p) {
    uint32_t a;
    asm("{ .reg .u64 t; cvta.to.shared.u64 t, %1; cvt.u32.u64 %0, t; }" : "=r"(a) : "l"(p));
    return a;
}
__device__ __forceinline__ void cp16(uint32_t s, const void* g) {
    asm volatile("cp.async.cg.shared.global [%0], [%1], 16;" :: "r"(s), "l"(g));
}
#define CP_COMMIT() asm volatile("cp.async.commit_group;" ::: "memory")
#define CP_WAIT1()  asm volatile("cp.async.wait_group 1;" ::: "memory")
#define CP_WAIT0()  asm volatile("cp.async.wait_group 0;" ::: "memory")

__device__ __forceinline__ void ldm4(uint32_t* r, uint32_t addr) {
    asm volatile("ldmatrix.sync.aligned.m8n8.x4.shared.b16 {%0,%1,%2,%3}, [%4];"
                 : "=r"(r[0]), "=r"(r[1]), "=r"(r[2]), "=r"(r[3]) : "r"(addr));
}
__device__ __forceinline__ void ldm4t(uint32_t* r, uint32_t addr) {
    asm volatile("ldmatrix.sync.aligned.m8n8.x4.trans.shared.b16 {%0,%1,%2,%3}, [%4];"
                 : "=r"(r[0]), "=r"(r[1]), "=r"(r[2]), "=r"(r[3]) : "r"(addr));
}
__device__ __forceinline__ void mma16816(float* d, const uint32_t* a,
                                         uint32_t b0, uint32_t b1) {
    asm volatile(
        "mma.sync.aligned.m16n8k16.row.col.f32.f16.f16.f32 "
        "{%0,%1,%2,%3}, {%4,%5,%6,%7}, {%8,%9}, {%0,%1,%2,%3};"
        : "+f"(d[0]), "+f"(d[1]), "+f"(d[2]), "+f"(d[3])
        : "r"(a[0]), "r"(a[1]), "r"(a[2]), "r"(a[3]), "r"(b0), "r"(b1));
}

// ---------------------------------------------------------------------------
// GEMM stage loader (A, B): 128x64 fp16 tiles, SW128 rows. 8 cp16/thread.
// ---------------------------------------------------------------------------
__device__ __forceinline__ void load_stage(
    uint32_t sbase,
    const __half* __restrict__ A, const __half* __restrict__ B,
    int m0, int n0, int kc, int tid)
{
#pragma unroll
    for (int t = 0; t < 4; t++) {
        int idx = t * 256 + tid;
        int row = idx >> 3;
        int c16 = idx & 7;
        uint32_t so = SWZ((uint32_t)(row * 128 + c16 * 16));
        cp16(sbase + OFF_A + so, A + (size_t)(m0 + row) * KDIM + kc + c16 * 8);
        cp16(sbase + OFF_B + so, B + (size_t)(n0 + row) * KDIM + kc + c16 * 8);
    }
}

// ---------------------------------------------------------------------------
// GEMM mainloop: acc[2][8][4] += A*B over K=1024. Single pass, 3-stage.
// ---------------------------------------------------------------------------
__device__ __forceinline__ void mma_mainloop(
    const __half* __restrict__ A, const __half* __restrict__ B,
    int m0, int n0, uint32_t sm32, float acc[2][8][4])
{
    const int tid = threadIdx.x;
    const int lane = tid & 31;
    const int wid = tid >> 5;
    const int wm = wid & 3;
    const int wn = wid >> 2;

    load_stage(sm32, A, B, m0, n0, 0, tid);
    CP_COMMIT();
    load_stage(sm32 + STAGE_BYTES, A, B, m0, n0, BK, tid);
    CP_COMMIT();

    const int a_row = (lane & 15);
    const int a_koff = (lane & 16) ? 8 : 0;
    const int b_row = (lane & 7) + ((lane & 16) >> 1);
    const int b_koff = (lane & 8) ? 8 : 0;

    const uint32_t aoff0 = (uint32_t)((wm * 32 + a_row) * 128 + a_koff * 2);
    const uint32_t aoff1 = aoff0 + 16 * 128;
    uint32_t boffs[4];
#pragma unroll
    for (int nb = 0; nb < 4; nb++)
        boffs[nb] = (uint32_t)((wn * 64 + nb * 16 + b_row) * 128 + b_koff * 2);

    int cur = 0, pre = 2;
    for (int c = 0; c < NCHUNK; c++) {
        if (c == NCHUNK - 1) CP_WAIT0(); else CP_WAIT1();
        __syncthreads();

        if (c + 2 < NCHUNK) {
            load_stage(sm32 + pre * STAGE_BYTES, A, B, m0, n0, (c + 2) * BK, tid);
            CP_COMMIT();
        }

        const uint32_t sb = sm32 + cur * STAGE_BYTES;
#pragma unroll
        for (int kk = 0; kk < BK; kk += 16) {
            uint32_t aa[2][4], bb[4][4];
            const uint32_t kb = (uint32_t)(kk * 2);
            ldm4(aa[0], sb + OFF_A + SWZ(aoff0 + kb));
            ldm4(aa[1], sb + OFF_A + SWZ(aoff1 + kb));
#pragma unroll
            for (int nb = 0; nb < 4; nb++)
                ldm4(bb[nb], sb + OFF_B + SWZ(boffs[nb] + kb));
#pragma unroll
            for (int ma = 0; ma < 2; ma++)
#pragma unroll
                for (int na = 0; na < 8; na++)
                    mma16816(acc[ma][na], aa[ma],
                             bb[na >> 1][(na & 1) * 2], bb[na >> 1][(na & 1) * 2 + 1]);
        }
        cur = (cur == NSTAGE - 1) ? 0 : cur + 1;
        pre = (pre == NSTAGE - 1) ? 0 : pre + 1;
    }
}

// ---------------------------------------------------------------------------
// QKV GEMM: epilogue applies elu+1 to q,k; writes q,k,v single fp16.
// ---------------------------------------------------------------------------
__global__ __launch_bounds__(256, 2) void gemm_qkv_mma() {
    extern __shared__ char smem[];
    const uint32_t sm32 = smem_u32(smem);
    const int m0 = blockIdx.y * BM;
    const int n0 = blockIdx.x * BN;

    float acc[2][8][4];
#pragma unroll
    for (int i = 0; i < 2; i++)
#pragma unroll
        for (int j = 0; j < 8; j++)
#pragma unroll
            for (int k = 0; k < 4; k++) acc[i][j][k] = 0.f;

    mma_mainloop(g_x16, g_wqkv, m0, n0, sm32, acc);

    const int tid = threadIdx.x;
    const int lane = tid & 31;
    const int wid = tid >> 5;
    const int wm = wid & 3, wn = wid >> 2;
    const int r0 = lane >> 2;
    const int c0 = (lane & 3) * 2;

#pragma unroll
    for (int ma = 0; ma < 2; ma++) {
#pragma unroll
        for (int na = 0; na < 8; na++) {
            const int colg = n0 + wn * 64 + na * 8 + c0;
            const int part = colg >> 10;
            const int h = (colg & 1023) >> 6;
            const int d = colg & 63;
            __half* dst = (part == 0) ? g_q16 : (part == 1) ? g_k16 : g_v;
            const bool feat = part < 2;
#pragma unroll
            for (int hf = 0; hf < 2; hf++) {
                const int m = m0 + wm * 32 + ma * 16 + r0 + hf * 8;
                const int bb = m >> 12, t = m & 4095;
                float v0 = acc[ma][na][hf * 2 + 0];
                float v1 = acc[ma][na][hf * 2 + 1];
                if (feat) { v0 = elu1(v0); v1 = elu1(v1); }
                size_t off = ((size_t)(bb * NH + h) * NTOK + t) * HD + d;
                *(__half2*)(dst + off) =
                    __halves2half2(__float2half_rn(v0), __float2half_rn(v1));
            }
        }
    }
}

// ---------------------------------------------------------------------------
// Proj GEMM: out = attn @ w_proj^T + bias
// ---------------------------------------------------------------------------
__global__ __launch_bounds__(256, 2) void gemm_proj_mma(const float* __restrict__ bias,
                                                        float* __restrict__ out) {
    extern __shared__ char smem[];
    const uint32_t sm32 = smem_u32(smem);
    const int m0 = blockIdx.y * BM;
    const int n0 = blockIdx.x * BN;

    float acc[2][8][4];
#pragma unroll
    for (int i = 0; i < 2; i++)
#pragma unroll
        for (int j = 0; j < 8; j++)
#pragma unroll
            for (int k = 0; k < 4; k++) acc[i][j][k] = 0.f;

    mma_mainloop(g_attn, g_wproj, m0, n0, sm32, acc);

    const int tid = threadIdx.x;
    const int lane = tid & 31;
    const int wid = tid >> 5;
    const int wm = wid & 3, wn = wid >> 2;
    const int r0 = lane >> 2;
    const int c0 = (lane & 3) * 2;

#pragma unroll
    for (int ma = 0; ma < 2; ma++) {
#pragma unroll
        for (int na = 0; na < 8; na++) {
            const int colg = n0 + wn * 64 + na * 8 + c0;
            const float b0 = bias[colg], b1 = bias[colg + 1];
#pragma unroll
            for (int hf = 0; hf < 2; hf++) {
                const int m = m0 + wm * 32 + ma * 16 + r0 + hf * 8;
                float2 o = make_float2(acc[ma][na][hf * 2 + 0] + b0,
                                       acc[ma][na][hf * 2 + 1] + b1);
                *(float2*)(out + (size_t)m * CDIM + colg) = o;
            }
        }
    }
}

// ---------------------------------------------------------------------------
// fp32 -> fp16 converts. which: 0 = x, 1 = w_qkv, 2 = w_proj
// ---------------------------------------------------------------------------
__global__ void conv16_kernel(const float* __restrict__ in, int which, int n) {
    __half* dst = (which == 0) ? g_x16 : (which == 1) ? g_wqkv : g_wproj;
    int i = (blockIdx.x * blockDim.x + threadIdx.x) * 4;
    if (i >= n) return;
    float4 v = *(const float4*)(in + i);
    *(__half2*)(dst + i)     = __halves2half2(__float2half_rn(v.x), __float2half_rn(v.y));
    *(__half2*)(dst + i + 2) = __halves2half2(__float2half_rn(v.z), __float2half_rn(v.w));
}

// ---------------------------------------------------------------------------
// kv via mma: per (bh, 1/16 split): kv[64d][64e] = k^T v; ksum side reduction.
// smem per stage: k(8K) v(8K). 8 warps = 2(m) x 4(n).
// ---------------------------------------------------------------------------
__device__ __forceinline__ void kv_load_stage(uint32_t sb, size_t gbase, int tid) {
#pragma unroll
    for (int t = 0; t < 2; t++) {
        int u = t * 256 + tid;
        int row = u >> 3, cb = u & 7;
        uint32_t so = SWZ((uint32_t)(row * 128 + cb * 16));
        size_t g = gbase + (size_t)row * HD + cb * 8;
        cp16(sb + so, g_k16 + g);
        cp16(sb + 8192 + so, g_v + g);
    }
}

__global__ __launch_bounds__(256, 2) void kv_mma_kernel() {
    extern __shared__ char smem[];
    const uint32_t sm32 = smem_u32(smem);
    const int tid = threadIdx.x, lane = tid & 31, wid = tid >> 5;
    const int bh = blockIdx.x >> 4, sp = blockIdx.x & 15;
    const int wm = wid & 1, wn = wid >> 1;
    const size_t nbase = (size_t)bh * NTOK + sp * (NTOK / KVSPLIT);

    float acc[2][2][4];
#pragma unroll
    for (int i = 0; i < 2; i++)
#pragma unroll
        for (int j = 0; j < 2; j++)
#pragma unroll
            for (int k = 0; k < 4; k++) acc[i][j][k] = 0.f;
    float ksacc = 0.f;
    const int ks_d = tid & 63, ks_q = tid >> 6;

    kv_load_stage(sm32, nbase * HD, tid);
    CP_COMMIT();

    const int l7 = lane & 7, lg = lane >> 3;
    const int an_off = ((lg >> 1) ? 8 : 0) + l7;
    const int ad_off = (lg & 1) ? 8 : 0;
    const int bn_off = ((lg & 1) ? 8 : 0) + l7;
    const int be_off = (lg >> 1) ? 8 : 0;
    const int d0 = wm * 32;
    const int e0 = wn * 16;

    for (int c = 0; c < 4; c++) {
        CP_WAIT0();
        __syncthreads();
        if (c + 1 < 4) {
            kv_load_stage(sm32 + ((c + 1) & 1) * KV_STAGE,
                          (nbase + (c + 1) * 64) * HD, tid);
            CP_COMMIT();
        }
        const uint32_t sb = sm32 + (c & 1) * KV_STAGE;
#pragma unroll
        for (int kk = 0; kk < 64; kk += 16) {
            uint32_t ak[2][4], bv[4];
#pragma unroll
            for (int ma = 0; ma < 2; ma++) {
                uint32_t ad = SWZ((uint32_t)((kk + an_off) * 128 +
                                             (d0 + ma * 16 + ad_off) * 2));
                ldm4t(ak[ma], sb + ad);
            }
            uint32_t bd = SWZ((uint32_t)((kk + bn_off) * 128 + (e0 + be_off) * 2));
            ldm4t(bv, sb + 8192 + bd);
#pragma unroll
            for (int ma = 0; ma < 2; ma++)
#pragma unroll
                for (int nb = 0; nb < 2; nb++)
                    mma16816(acc[ma][nb], ak[ma], bv[nb * 2], bv[nb * 2 + 1]);
        }
        // ksum side reduction over this chunk
#pragma unroll
        for (int nn = 0; nn < 16; nn++) {
            int n = ks_q * 16 + nn;
            uint32_t off = SWZ((uint32_t)(n * 128 + ks_d * 2));
            ksacc += __half2float(*(const __half*)(smem + (c & 1) * KV_STAGE + off));
        }
    }

    float* kssm = (float*)(smem + 2 * KV_STAGE);
    kssm[ks_q * 64 + ks_d] = ksacc;
    __syncthreads();
    if (tid < 64) {
        float s = kssm[tid] + kssm[64 + tid] + kssm[128 + tid] + kssm[192 + tid];
        g_ksum_part[(sp * NBH + bh) * HD + tid] = s;
    }

    const int r0 = lane >> 2, c0 = (lane & 3) * 2;
    float* kvout = g_kv_part + (size_t)(sp * NBH + bh) * (HD * HD);
#pragma unroll
    for (int ma = 0; ma < 2; ma++)
#pragma unroll
        for (int nb = 0; nb < 2; nb++)
#pragma unroll
            for (int hf = 0; hf < 2; hf++) {
                int d = d0 + ma * 16 + r0 + hf * 8;
                int e = e0 + nb * 8 + c0;
                *(float2*)(kvout + d * 64 + e) =
                    make_float2(acc[ma][nb][hf * 2], acc[ma][nb][hf * 2 + 1]);
            }
}

// ---------------------------------------------------------------------------
// kv reduce: sum partials, write kvT fp16 ([e][d]) + ksum fp32.
// ---------------------------------------------------------------------------
__global__ __launch_bounds__(256) void kv_reduce_kernel() {
    __shared__ float kvsm[64][65];
    const int bh = blockIdx.x;
    const int tid = threadIdx.x;
    for (int j = tid; j < HD * HD; j += 256) {
        float s = 0.f;
#pragma unroll
        for (int p = 0; p < KVSPLIT; p++)
            s += g_kv_part[(size_t)(p * NBH + bh) * (HD * HD) + j];
        kvsm[j >> 6][j & 63] = s;
    }
    if (tid < HD) {
        float s = 0.f;
#pragma unroll
        for (int p = 0; p < KVSPLIT; p++)
            s += g_ksum_part[(p * NBH + bh) * HD + tid];
        g_ksum[bh * HD + tid] = s;
    }
    __syncthreads();
    for (int j = tid; j < HD * HD; j += 256) {
        int e = j >> 6, d = j & 63;
        g_kvT[(size_t)bh * (HD * HD) + j] = __float2half_rn(kvsm[d][e]);
    }
}

// ---------------------------------------------------------------------------
// attn via mma: num = q @ kvT^T; /(q.ksum+eps); writes attn fp16.
// 8 warps = 4(m) x 2(n).
// ---------------------------------------------------------------------------
__global__ __launch_bounds__(256, 2) void attn_mma_kernel() {
    extern __shared__ char smem[];
    const uint32_t sm32 = smem_u32(smem);
    const int tid = threadIdx.x, lane = tid & 31, wid = tid >> 5;
    const int bh = blockIdx.y;
    const int bb = bh >> 4, h = bh & 15;
    const int row0 = blockIdx.x * 128;
    const int wm = wid & 3, wn = wid >> 2;

    {
        size_t qbase = ((size_t)bh * NTOK + row0) * HD;
#pragma unroll
        for (int t = 0; t < 4; t++) {
            int u = t * 256 + tid;
            int row = u >> 3, cb = u & 7;
            uint32_t so = SWZ((uint32_t)(row * 128 + cb * 16));
            cp16(sm32 + AT_Q + so, g_q16 + qbase + (size_t)row * HD + cb * 8);
        }
#pragma unroll
        for (int t = 0; t < 2; t++) {
            int u = t * 256 + tid;
            int row = u >> 3, cb = u & 7;
            uint32_t so = SWZ((uint32_t)(row * 128 + cb * 16));
            cp16(sm32 + AT_KV + so,
                 g_kvT + (size_t)bh * (HD * HD) + (size_t)row * HD + cb * 8);
        }
        if (tid < 64) ((float*)(smem + AT_KSUM))[tid] = g_ksum[bh * HD + tid];
        CP_COMMIT();
        CP_WAIT0();
        __syncthreads();
    }

    // qk denominator (fp32)
    {
        int row = tid >> 1, hh = tid & 1;
        float s = 0.f;
        const float* kss = (const float*)(smem + AT_KSUM);
#pragma unroll
        for (int dd = 0; dd < 32; dd++) {
            int d = hh * 32 + dd;
            uint32_t off = SWZ((uint32_t)(row * 128 + d * 2));
            s += __half2float(*(const __half*)(smem + AT_Q + off)) * kss[d];
        }
        s += __shfl_xor_sync(0xFFFFFFFFu, s, 1);
        if (hh == 0) ((float*)(smem + AT_INV))[row] = 1.f / (s + 1e-8f);
        __syncthreads();
    }

    float acc[2][4][4];
#pragma unroll
    for (int i = 0; i < 2; i++)
#pragma unroll
        for (int j = 0; j < 4; j++)
#pragma unroll
            for (int k = 0; k < 4; k++) acc[i][j][k] = 0.f;

    const int a_row = lane & 15;
    const int a_koff = (lane & 16) ? 8 : 0;
    const int b_row = (lane & 7) + ((lane & 16) >> 1);
    const int b_koff = (lane & 8) ? 8 : 0;

#pragma unroll
    for (int kk = 0; kk < 64; kk += 16) {
        uint32_t qa[2][4], kvb[2][4];
#pragma unroll
        for (int ma = 0; ma < 2; ma++) {
            uint32_t ad = SWZ((uint32_t)((wm * 32 + ma * 16 + a_row) * 128 +
                                         (kk + a_koff) * 2));
            ldm4(qa[ma], sm32 + AT_Q + ad);
        }
#pragma unroll
        for (int nb = 0; nb < 2; nb++) {
            uint32_t bd = SWZ((uint32_t)((wn * 32 + nb * 16 + b_row) * 128 +
                                         (kk + b_koff) * 2));
            ldm4(kvb[nb], sm32 + AT_KV + bd);
        }
#pragma unroll
        for (int ma = 0; ma < 2; ma++)
#pragma unroll
            for (int na = 0; na < 4; na++)
                mma16816(acc[ma][na], qa[ma],
                         kvb[na >> 1][(na & 1) * 2], kvb[na >> 1][(na & 1) * 2 + 1]);
    }

    const int r0 = lane >> 2, c0 = (lane & 3) * 2;
    const float* invp = (const float*)(smem + AT_INV);
#pragma unroll
    for (int ma = 0; ma < 2; ma++)
#pragma unroll
        for (int na = 0; na < 4; na++)
#pragma unroll
            for (int hf = 0; hf < 2; hf++) {
                int row = wm * 32 + ma * 16 + r0 + hf * 8;
                float iv = invp[row];
                int e = wn * 32 + na * 8 + c0;
                float v0 = acc[ma][na][hf * 2 + 0] * iv;
                float v1 = acc[ma][na][hf * 2 + 1] * iv;
                size_t ob = ((size_t)(bb * NTOK + row0 + row)) * CDIM + h * HD + e;
                *(__half2*)(g_attn + ob) =
                    __halves2half2(__float2half_rn(v0), __float2half_rn(v1));
            }
}

// ---------------------------------------------------------------------------
extern "C" void kernel_launch(void* const* d_in, const int* in_sizes, int n_in,
                              void* d_out, int out_size) {
    const float* x      = (const float*)d_in[0];
    const float* w_qkv  = (const float*)d_in[1];
    const float* w_proj = (const float*)d_in[2];
    const float* b_proj = (const float*)d_in[3];
    float* out = (float*)d_out;

    cudaFuncSetAttribute(gemm_qkv_mma, cudaFuncAttributeMaxDynamicSharedMemorySize,
                         SMEM_GEMM_BYTES);
    cudaFuncSetAttribute(gemm_proj_mma, cudaFuncAttributeMaxDynamicSharedMemorySize,
                         SMEM_GEMM_BYTES);
    cudaFuncSetAttribute(kv_mma_kernel, cudaFuncAttributeMaxDynamicSharedMemorySize,
                         SMEM_KV_BYTES);
    cudaFuncSetAttribute(attn_mma_kernel, cudaFuncAttributeMaxDynamicSharedMemorySize,
                         SMEM_AT_BYTES);

    conv16_kernel<<<(MTOT * KDIM) / 1024, 256>>>(x, 0, MTOT * KDIM);
    conv16_kernel<<<(NQKV * KDIM) / 1024, 256>>>(w_qkv, 1, NQKV * KDIM);
    conv16_kernel<<<(CDIM * KDIM) / 1024, 256>>>(w_proj, 2, CDIM * KDIM);

    gemm_qkv_mma<<<dim3(NQKV / BN, MTOT / BM), 256, SMEM_GEMM_BYTES>>>();

    kv_mma_kernel<<<NBH * KVSPLIT, 256, SMEM_KV_BYTES>>>();
    kv_reduce_kernel<<<NBH, 256>>>();

    attn_mma_kernel<<<dim3(NTOK / 128, NBH), 256, SMEM_AT_BYTES>>>();

    gemm_proj_mma<<<dim3(CDIM / BN, MTOT / BM), 256, SMEM_GEMM_BYTES>>>(b_proj, out);
}